// round 1
// baseline (speedup 1.0000x reference)
#include <cuda_runtime.h>
#include <math.h>

// Problem constants
#define Bsz 32
#define Ssz 512
#define Dsz 512
#define Hh  8
#define HDim 64
#define Mrows (Bsz*Ssz)          // 16384
#define NEG_SLOPE 0.2f

// ---------------------------------------------------------------------------
// Scratch (static __device__ arrays; allocation is forbidden)
// ---------------------------------------------------------------------------
__device__ float g_h   [Bsz*Hh*Ssz*HDim];   // (B,H,S,HD) linear-projected heads
__device__ float g_src [Bsz*Hh*Ssz];
__device__ float g_dst [Bsz*Hh*Ssz];
__device__ float g_att [Bsz*Hh*Ssz*HDim];   // attention output, (B,H,S,HD)
__device__ float g_y   [Mrows*Dsz];         // post-LN1 activations
__device__ float g_ff  [Mrows*2*Dsz];       // GeLU(ff1) activations
__device__ float g_pre2[Mrows*Dsz];         // ff2 out + residual (pre-LN2)

// ---------------------------------------------------------------------------
// SGEMM: C = A @ W^T + bias, NT layout (both row-major, K contiguous).
// 128x128 block tile, BK=16, 256 threads, 8x8 per-thread tile (split-N frags),
// double-buffered smem with register prefetch.
// EPI: 1 = write to g_h with (B,H,S,HD) scatter (A = param)
//      2 = exact GeLU, A = g_y, C = g_ff
//      3 = + residual g_y, A = g_ff, C = g_pre2
// ---------------------------------------------------------------------------
template<int EPI>
__global__ __launch_bounds__(256, 2) void sgemm_nt_kernel(
    const float* __restrict__ A_param,
    const float* __restrict__ W,
    const float* __restrict__ bias,
    int M, int N, int K)
{
    __shared__ float As[2][16][128];
    __shared__ float Bs[2][16][128];

    const float* A = (EPI == 1) ? A_param : (EPI == 2 ? (const float*)g_y
                                                      : (const float*)g_ff);

    const int tid  = threadIdx.x;
    const int bm   = blockIdx.y << 7;
    const int bn   = blockIdx.x << 7;
    const int lrow = tid >> 2;            // 0..63
    const int lcol = (tid & 3) << 2;      // k offset {0,4,8,12}

    const float* Ap = A + (size_t)(bm + lrow) * K + lcol;
    const float* Wp = W + (size_t)(bn + lrow) * K + lcol;

    const int ty = tid >> 4;              // 0..15 -> rows ty*8
    const int tx = tid & 15;              // 0..15 -> cols tx*4 and tx*4+64

    float acc[8][8];
    #pragma unroll
    for (int i = 0; i < 8; i++)
        #pragma unroll
        for (int j = 0; j < 8; j++) acc[i][j] = 0.f;

    float4 pa0, pa1, pb0, pb1;
    auto stage = [&](int b_) {
        As[b_][lcol+0][lrow]    = pa0.x; As[b_][lcol+1][lrow]    = pa0.y;
        As[b_][lcol+2][lrow]    = pa0.z; As[b_][lcol+3][lrow]    = pa0.w;
        As[b_][lcol+0][lrow+64] = pa1.x; As[b_][lcol+1][lrow+64] = pa1.y;
        As[b_][lcol+2][lrow+64] = pa1.z; As[b_][lcol+3][lrow+64] = pa1.w;
        Bs[b_][lcol+0][lrow]    = pb0.x; Bs[b_][lcol+1][lrow]    = pb0.y;
        Bs[b_][lcol+2][lrow]    = pb0.z; Bs[b_][lcol+3][lrow]    = pb0.w;
        Bs[b_][lcol+0][lrow+64] = pb1.x; Bs[b_][lcol+1][lrow+64] = pb1.y;
        Bs[b_][lcol+2][lrow+64] = pb1.z; Bs[b_][lcol+3][lrow+64] = pb1.w;
    };

    // prologue
    pa0 = *(const float4*)(Ap);
    pa1 = *(const float4*)(Ap + (size_t)64 * K);
    pb0 = *(const float4*)(Wp);
    pb1 = *(const float4*)(Wp + (size_t)64 * K);
    stage(0);
    __syncthreads();

    const int nk = K >> 4;
    int buf = 0;
    for (int kt = 0; kt < nk; kt++) {
        if (kt + 1 < nk) {
            const float* Ap2 = Ap + (kt + 1) * 16;
            const float* Wp2 = Wp + (kt + 1) * 16;
            pa0 = *(const float4*)(Ap2);
            pa1 = *(const float4*)(Ap2 + (size_t)64 * K);
            pb0 = *(const float4*)(Wp2);
            pb1 = *(const float4*)(Wp2 + (size_t)64 * K);
        }
        #pragma unroll
        for (int kk = 0; kk < 16; kk++) {
            float4 a0 = *(const float4*)&As[buf][kk][ty << 3];
            float4 a1 = *(const float4*)&As[buf][kk][(ty << 3) + 4];
            float4 b0 = *(const float4*)&Bs[buf][kk][tx << 2];
            float4 b1 = *(const float4*)&Bs[buf][kk][(tx << 2) + 64];
            float ar[8] = {a0.x,a0.y,a0.z,a0.w,a1.x,a1.y,a1.z,a1.w};
            float br[8] = {b0.x,b0.y,b0.z,b0.w,b1.x,b1.y,b1.z,b1.w};
            #pragma unroll
            for (int i = 0; i < 8; i++)
                #pragma unroll
                for (int j = 0; j < 8; j++)
                    acc[i][j] = fmaf(ar[i], br[j], acc[i][j]);
        }
        if (kt + 1 < nk) {
            buf ^= 1;
            stage(buf);
            __syncthreads();
        }
    }

    // epilogue
    const int c0 = bn + (tx << 2);
    float4 bb0 = *(const float4*)&bias[c0];
    float4 bb1 = *(const float4*)&bias[c0 + 64];
    const int row0 = bm + (ty << 3);

    #pragma unroll
    for (int i = 0; i < 8; i++) {
        const int m = row0 + i;
        #pragma unroll
        for (int h2 = 0; h2 < 2; h2++) {
            const int n = c0 + h2 * 64;
            const float4 bb = h2 ? bb1 : bb0;
            float4 v;
            v.x = acc[i][h2*4+0] + bb.x;
            v.y = acc[i][h2*4+1] + bb.y;
            v.z = acc[i][h2*4+2] + bb.z;
            v.w = acc[i][h2*4+3] + bb.w;
            if (EPI == 2) {           // exact GeLU
                v.x = 0.5f*v.x*(1.f + erff(v.x*0.70710678118654752f));
                v.y = 0.5f*v.y*(1.f + erff(v.y*0.70710678118654752f));
                v.z = 0.5f*v.z*(1.f + erff(v.z*0.70710678118654752f));
                v.w = 0.5f*v.w*(1.f + erff(v.w*0.70710678118654752f));
            }
            if (EPI == 3) {           // + residual (post-LN1 y)
                float4 rr = *(const float4*)&g_y[(size_t)m * N + n];
                v.x += rr.x; v.y += rr.y; v.z += rr.z; v.w += rr.w;
            }
            if (EPI == 1) {           // scatter to (B,H,S,HD)
                const int bI = m >> 9, sI = m & 511;
                const int hh = n >> 6, hd = n & 63;
                *(float4*)&g_h[((((bI << 3) + hh) << 9) + sI) * HDim + hd] = v;
            } else if (EPI == 2) {
                *(float4*)&g_ff[(size_t)m * N + n] = v;
            } else if (EPI == 3) {
                *(float4*)&g_pre2[(size_t)m * N + n] = v;
            }
        }
    }
}

// ---------------------------------------------------------------------------
// src/dst projections: one warp per (b,h,s) row of h
// ---------------------------------------------------------------------------
__global__ __launch_bounds__(128) void src_dst_kernel(const float* __restrict__ a_w)
{
    const int row  = blockIdx.x * 4 + (threadIdx.x >> 5);
    const int lane = threadIdx.x & 31;
    const float* hrow = g_h + (size_t)row * HDim;
    const float v0 = hrow[lane], v1 = hrow[lane + 32];
    float s = v0 * a_w[lane]      + v1 * a_w[lane + 32];
    float d = v0 * a_w[64 + lane] + v1 * a_w[96 + lane];
    #pragma unroll
    for (int off = 16; off; off >>= 1) {
        s += __shfl_xor_sync(0xffffffffu, s, off);
        d += __shfl_xor_sync(0xffffffffu, d, off);
    }
    if (lane == 0) { g_src[row] = s; g_dst[row] = d; }
}

// ---------------------------------------------------------------------------
// Fused GAT attention per (b,h): softmax_j(leaky_relu(src_i + dst_j)) @ h.
// Factorized exp:  exp(LR(s+d)) = (s+d>=0) ? e^s * e^d : e^{0.2s} * e^{0.2d}
// Block: 64 rows (i) x full j range; thread (r,q): row r, cols {4q+16k}.
// ---------------------------------------------------------------------------
__global__ __launch_bounds__(256) void attn_kernel()
{
    const int bh  = blockIdx.y;          // 0..255
    const int i0  = blockIdx.x << 6;     // row-tile start
    const int tid = threadIdx.x;

    __shared__ float dstRaw[512], dstE1[512], dstE2[512];
    __shared__ float srcS[64];
    __shared__ float red[256];
    __shared__ float hT[64][64];

    const float* srcp = g_src + bh * Ssz;
    const float* dstp = g_dst + bh * Ssz;
    for (int u = tid; u < 512; u += 256) {
        const float dv = dstp[u];
        dstRaw[u] = dv;
        dstE1[u]  = __expf(dv);
        dstE2[u]  = __expf(NEG_SLOPE * dv);
    }
    if (tid < 64) srcS[tid] = srcp[i0 + tid];
    __syncthreads();

    const int r = tid >> 2, q = tid & 3;
    const float sv  = srcS[r];
    const float e1s = __expf(sv), e2s = __expf(NEG_SLOPE * sv);

    // denominator (interleaved j so lanes hit distinct banks)
    float ps = 0.f;
    #pragma unroll 4
    for (int jj = 0; jj < 128; jj++) {
        const int j = q + (jj << 2);
        const float d = dstRaw[j];
        ps += ((sv + d) >= 0.f) ? e1s * dstE1[j] : e2s * dstE2[j];
    }
    red[tid] = ps;
    __syncthreads();
    const float inv = 1.0f / (red[(r<<2)] + red[(r<<2)+1] + red[(r<<2)+2] + red[(r<<2)+3]);

    float acc[16];
    #pragma unroll
    for (int c = 0; c < 16; c++) acc[c] = 0.f;

    const float* hbase = g_h + (size_t)bh * Ssz * HDim;
    for (int jt = 0; jt < Ssz; jt += 64) {
        __syncthreads();
        #pragma unroll
        for (int u = 0; u < 4; u++) {
            const int v  = tid + (u << 8);      // float4 id 0..1023
            const int jr = v >> 4;
            const int cc = (v & 15) << 2;
            *(float4*)&hT[jr][cc] = *(const float4*)&hbase[(size_t)(jt + jr) * HDim + cc];
        }
        __syncthreads();
        #pragma unroll 4
        for (int jj = 0; jj < 64; jj++) {
            const float d = dstRaw[jt + jj];
            const float w = (((sv + d) >= 0.f) ? e1s * dstE1[jt + jj]
                                               : e2s * dstE2[jt + jj]) * inv;
            #pragma unroll
            for (int k = 0; k < 4; k++) {
                const float4 hv = *(const float4*)&hT[jj][(q << 2) + (k << 4)];
                acc[k*4+0] = fmaf(w, hv.x, acc[k*4+0]);
                acc[k*4+1] = fmaf(w, hv.y, acc[k*4+1]);
                acc[k*4+2] = fmaf(w, hv.z, acc[k*4+2]);
                acc[k*4+3] = fmaf(w, hv.w, acc[k*4+3]);
            }
        }
    }

    float* outp = g_att + (size_t)(bh * Ssz + i0 + r) * HDim;
    #pragma unroll
    for (int k = 0; k < 4; k++)
        *(float4*)&outp[(q << 2) + (k << 4)] =
            make_float4(acc[k*4+0], acc[k*4+1], acc[k*4+2], acc[k*4+3]);
}

// ---------------------------------------------------------------------------
// LayerNorms (block per row of 512; thread handles d = tid, tid+256)
// ---------------------------------------------------------------------------
__device__ __forceinline__ void block_meanvar(float v0, float v1, int tid,
                                              float& mean, float& rstd)
{
    float s1 = v0 + v1;
    float s2 = v0 * v0 + v1 * v1;
    #pragma unroll
    for (int off = 16; off; off >>= 1) {
        s1 += __shfl_xor_sync(0xffffffffu, s1, off);
        s2 += __shfl_xor_sync(0xffffffffu, s2, off);
    }
    __shared__ float rs[8], rq[8];
    __shared__ float mn_s, rstd_s;
    const int lane = tid & 31, w = tid >> 5;
    if (lane == 0) { rs[w] = s1; rq[w] = s2; }
    __syncthreads();
    if (tid == 0) {
        float a = 0.f, c = 0.f;
        #pragma unroll
        for (int i = 0; i < 8; i++) { a += rs[i]; c += rq[i]; }
        const float m = a * (1.0f / 512.0f);
        const float var = c * (1.0f / 512.0f) - m * m;
        mn_s = m;
        rstd_s = rsqrtf(var + 1e-5f);
    }
    __syncthreads();
    mean = mn_s; rstd = rstd_s;
}

__global__ __launch_bounds__(256) void ln1_kernel(
    const float* __restrict__ x,
    const float* __restrict__ gw, const float* __restrict__ bw)
{
    const int m = blockIdx.x, tid = threadIdx.x;
    const int bb = m >> 9, s = m & 511;
    float v0, v1;
    {
        int d = tid;
        v0 = g_att[((((bb << 3) + (d >> 6)) << 9) + s) * HDim + (d & 63)]
           + x[(size_t)m * Dsz + d];
        d = tid + 256;
        v1 = g_att[((((bb << 3) + (d >> 6)) << 9) + s) * HDim + (d & 63)]
           + x[(size_t)m * Dsz + d];
    }
    float mean, rstd;
    block_meanvar(v0, v1, tid, mean, rstd);
    g_y[(size_t)m * Dsz + tid]       = (v0 - mean) * rstd * gw[tid]       + bw[tid];
    g_y[(size_t)m * Dsz + tid + 256] = (v1 - mean) * rstd * gw[tid + 256] + bw[tid + 256];
}

__global__ __launch_bounds__(256) void ln2_kernel(
    const float* __restrict__ gw, const float* __restrict__ bw,
    float* __restrict__ out)
{
    const int m = blockIdx.x, tid = threadIdx.x;
    const float v0 = g_pre2[(size_t)m * Dsz + tid];
    const float v1 = g_pre2[(size_t)m * Dsz + tid + 256];
    float mean, rstd;
    block_meanvar(v0, v1, tid, mean, rstd);
    out[(size_t)m * Dsz + tid]       = (v0 - mean) * rstd * gw[tid]       + bw[tid];
    out[(size_t)m * Dsz + tid + 256] = (v1 - mean) * rstd * gw[tid + 256] + bw[tid + 256];
}

// ---------------------------------------------------------------------------
// Launch. Input order: x, adj, w_W, w_b, a_w, sem_W, sem_b, ff1_W, ff1_b,
//                      ff2_W, ff2_b, ln1_g, ln1_b, ln2_g, ln2_b
// adj/sem_W/sem_b are provably dead (softmax output can never be exactly 0,
// so the mask is the identity) and are not read.
// ---------------------------------------------------------------------------
extern "C" void kernel_launch(void* const* d_in, const int* in_sizes, int n_in,
                              void* d_out, int out_size)
{
    const float* x     = (const float*)d_in[0];
    const float* w_W   = (const float*)d_in[2];
    const float* w_b   = (const float*)d_in[3];
    const float* a_w   = (const float*)d_in[4];
    const float* ff1_W = (const float*)d_in[7];
    const float* ff1_b = (const float*)d_in[8];
    const float* ff2_W = (const float*)d_in[9];
    const float* ff2_b = (const float*)d_in[10];
    const float* ln1_g = (const float*)d_in[11];
    const float* ln1_b = (const float*)d_in[12];
    const float* ln2_g = (const float*)d_in[13];
    const float* ln2_b = (const float*)d_in[14];
    float* out = (float*)d_out;

    // 1) h = x @ w_W^T + w_b  -> g_h (B,H,S,HD)
    sgemm_nt_kernel<1><<<dim3(Dsz/128, Mrows/128), 256>>>(x, w_W, w_b, Mrows, Dsz, Dsz);
    // 2) src/dst projections
    src_dst_kernel<<<(Bsz*Hh*Ssz)/4, 128>>>(a_w);
    // 3) fused GAT attention -> g_att
    attn_kernel<<<dim3(Ssz/64, Bsz*Hh), 256>>>();
    // 4) LN1(att + x) -> g_y
    ln1_kernel<<<Mrows, 256>>>(x, ln1_g, ln1_b);
    // 5) g_ff = GeLU(g_y @ ff1_W^T + ff1_b)
    sgemm_nt_kernel<2><<<dim3(2*Dsz/128, Mrows/128), 256>>>(nullptr, ff1_W, ff1_b, Mrows, 2*Dsz, Dsz);
    // 6) g_pre2 = g_ff @ ff2_W^T + ff2_b + g_y
    sgemm_nt_kernel<3><<<dim3(Dsz/128, Mrows/128), 256>>>(nullptr, ff2_W, ff2_b, Mrows, Dsz, 2*Dsz);
    // 7) LN2 -> out
    ln2_kernel<<<Mrows, 256>>>(ln2_g, ln2_b, out);
}

// round 3
// speedup vs baseline: 1.5393x; 1.5393x over previous
#include <cuda_runtime.h>
#include <math.h>
#include <stdint.h>

// Problem constants
#define Bsz 32
#define Ssz 512
#define Dsz 512
#define Hh  8
#define HDim 64
#define Mrows (Bsz*Ssz)          // 16384
#define NEG_SLOPE 0.2f

// ---------------------------------------------------------------------------
// Scratch (static __device__ arrays; allocation is forbidden)
// ---------------------------------------------------------------------------
__device__ float g_h   [Bsz*Hh*Ssz*HDim];   // (B,H,S,HD) linear-projected heads
__device__ float g_src [Bsz*Hh*Ssz];
__device__ float g_dst [Bsz*Hh*Ssz];
__device__ float g_att [Bsz*Hh*Ssz*HDim];   // attention output, (B,H,S,HD)
__device__ float g_y   [Mrows*Dsz];         // post-LN1 activations
__device__ float g_ff  [Mrows*2*Dsz];       // GeLU(ff1) activations
__device__ float g_pre2[Mrows*Dsz];         // ff2 out + residual (pre-LN2)

// ---------------------------------------------------------------------------
// mma.sync tf32 helpers (PTX ISA sm_80+, legal on .target sm_103)
// ---------------------------------------------------------------------------
__device__ __forceinline__ uint32_t tf32r(float x) {
    uint32_t r;
    asm("cvt.rna.tf32.f32 %0, %1;" : "=r"(r) : "f"(x));
    return r;
}
__device__ __forceinline__ void mma8(float* c, const uint32_t* a, const uint32_t* b) {
    asm volatile(
        "mma.sync.aligned.m16n8k8.row.col.f32.tf32.tf32.f32 "
        "{%0,%1,%2,%3}, {%4,%5,%6,%7}, {%8,%9}, {%0,%1,%2,%3};"
        : "+f"(c[0]), "+f"(c[1]), "+f"(c[2]), "+f"(c[3])
        : "r"(a[0]), "r"(a[1]), "r"(a[2]), "r"(a[3]), "r"(b[0]), "r"(b[1]));
}

// ---------------------------------------------------------------------------
// Tensor-core GEMM: C = A @ W^T + bias (both row-major, K contiguous).
// CTA 128x128, BK=32, 256 threads (8 warps, warp tile 64x32), tf32 mma.sync,
// double-buffered smem with pad-4 rows (LDK=36 -> conflict-free frag loads).
// EPI: 1 = write to g_h with (B,H,S,HD) scatter (A = param)
//      2 = exact GeLU, A = g_y, C = g_ff
//      3 = + residual g_y, A = g_ff, C = g_pre2
// ---------------------------------------------------------------------------
#define BK   32
#define LDK  36                    // padded row stride in floats
#define SSTG (128*LDK)             // u32 per stage per matrix (4608)
#define MM_SMEM_BYTES (4*SSTG*4)   // A[2] + B[2] = 73728 B

template<int EPI>
__global__ __launch_bounds__(256, 1) void mm_mma(
    const float* __restrict__ Ain, const float* __restrict__ W,
    const float* __restrict__ bias, int N, int K)
{
    extern __shared__ uint32_t smbuf[];
    uint32_t* As = smbuf;              // [2][SSTG]
    uint32_t* Bs = smbuf + 2*SSTG;     // [2][SSTG]

    const float* A = (EPI == 1) ? Ain : (EPI == 2 ? (const float*)g_y
                                                  : (const float*)g_ff);

    const int tid  = threadIdx.x;
    const int wid  = tid >> 5;
    const int lane = tid & 31;
    const int g    = lane >> 2;        // groupID
    const int t    = lane & 3;         // threadID_in_group
    const int bm   = blockIdx.y << 7;
    const int bn   = blockIdx.x << 7;
    const int wm   = (wid & 1) << 6;   // warp row offset (0/64)
    const int wn   = (wid >> 1) << 5;  // warp col offset (0/32/64/96)

    // producer indexing: 1024 float4 per matrix per stage
    const int pr  = tid >> 1;          // 0..127 (row, 2 threads per row)
    const int pc0 = (tid & 1) << 2;    // float4 col 0 or 4

    float acc[4][4][4];
    #pragma unroll
    for (int mi = 0; mi < 4; mi++)
        #pragma unroll
        for (int ni = 0; ni < 4; ni++)
            #pragma unroll
            for (int c = 0; c < 4; c++) acc[mi][ni][c] = 0.f;

    float4 pa[4], pb[4];
    auto fetch = [&](int kt) {
        const int k0 = kt << 5;
        #pragma unroll
        for (int u = 0; u < 4; u++) {
            // rows pr, cols k0 + 4*(pc0+u)... arrange: each thread 4 float4 of A
            // A tile: 128 rows x 8 float4-cols; thread covers (pr, pc0+ (u&... )
            // simpler: linear idx = tid + u*256 -> r=idx>>3, c4=idx&7
            const int idx = tid + (u << 8);
            const int r = idx >> 3, c4 = idx & 7;
            pa[u] = *(const float4*)(A + (size_t)(bm + r) * K + k0 + (c4 << 2));
            pb[u] = *(const float4*)(W + (size_t)(bn + r) * K + k0 + (c4 << 2));
        }
    };
    auto stage = [&](int buf) {
        uint32_t* Ad = As + buf * SSTG;
        uint32_t* Bd = Bs + buf * SSTG;
        #pragma unroll
        for (int u = 0; u < 4; u++) {
            const int idx = tid + (u << 8);
            const int r = idx >> 3, c4 = idx & 7;
            const int o = r * LDK + (c4 << 2);
            *(uint4*)(Ad + o) = make_uint4(tf32r(pa[u].x), tf32r(pa[u].y),
                                           tf32r(pa[u].z), tf32r(pa[u].w));
            *(uint4*)(Bd + o) = make_uint4(tf32r(pb[u].x), tf32r(pb[u].y),
                                           tf32r(pb[u].z), tf32r(pb[u].w));
        }
    };

    const int nkt = K >> 5;
    fetch(0);
    stage(0);
    __syncthreads();

    int buf = 0;
    for (int kt = 0; kt < nkt; kt++) {
        if (kt + 1 < nkt) fetch(kt + 1);

        const uint32_t* Ab = As + buf * SSTG;
        const uint32_t* Bb = Bs + buf * SSTG;
        #pragma unroll
        for (int kc = 0; kc < 4; kc++) {
            const int kb = kc << 3;
            uint32_t af[4][4], bf[4][2];
            #pragma unroll
            for (int mi = 0; mi < 4; mi++) {
                const uint32_t* p = Ab + (wm + (mi << 4) + g) * LDK + kb + t;
                af[mi][0] = p[0];
                af[mi][1] = p[8 * LDK];
                af[mi][2] = p[4];
                af[mi][3] = p[8 * LDK + 4];
            }
            #pragma unroll
            for (int ni = 0; ni < 4; ni++) {
                const uint32_t* p = Bb + (wn + (ni << 3) + g) * LDK + kb + t;
                bf[ni][0] = p[0];
                bf[ni][1] = p[4];
            }
            #pragma unroll
            for (int mi = 0; mi < 4; mi++)
                #pragma unroll
                for (int ni = 0; ni < 4; ni++)
                    mma8(acc[mi][ni], af[mi], bf[ni]);
        }

        if (kt + 1 < nkt) {
            buf ^= 1;
            stage(buf);
            __syncthreads();
        }
    }

    // ---------------- epilogue ----------------
    #pragma unroll
    for (int ni = 0; ni < 4; ni++) {
        const int col = bn + wn + (ni << 3) + (t << 1);
        const float2 bb = *(const float2*)&bias[col];
        #pragma unroll
        for (int mi = 0; mi < 4; mi++) {
            #pragma unroll
            for (int half = 0; half < 2; half++) {
                const int row = bm + wm + (mi << 4) + g + (half << 3);
                float2 v;
                v.x = acc[mi][ni][half*2+0] + bb.x;
                v.y = acc[mi][ni][half*2+1] + bb.y;
                if (EPI == 2) {
                    v.x = 0.5f*v.x*(1.f + erff(v.x*0.70710678118654752f));
                    v.y = 0.5f*v.y*(1.f + erff(v.y*0.70710678118654752f));
                }
                if (EPI == 3) {
                    const float2 rr = *(const float2*)&g_y[(size_t)row * Dsz + col];
                    v.x += rr.x; v.y += rr.y;
                }
                if (EPI == 1) {
                    const int bI = row >> 9, sI = row & 511;
                    const int hh = col >> 6, hd = col & 63;
                    *(float2*)&g_h[((size_t)(((bI << 3) + hh) << 9) + sI) * HDim + hd] = v;
                } else if (EPI == 2) {
                    *(float2*)&g_ff[(size_t)row * N + col] = v;
                } else {
                    *(float2*)&g_pre2[(size_t)row * Dsz + col] = v;
                }
            }
        }
    }
}

// ---------------------------------------------------------------------------
// src/dst projections: one warp per (b,h,s) row of h
// ---------------------------------------------------------------------------
__global__ __launch_bounds__(128) void src_dst_kernel(const float* __restrict__ a_w)
{
    const int row  = blockIdx.x * 4 + (threadIdx.x >> 5);
    const int lane = threadIdx.x & 31;
    const float* hrow = g_h + (size_t)row * HDim;
    const float v0 = hrow[lane], v1 = hrow[lane + 32];
    float s = v0 * a_w[lane]      + v1 * a_w[lane + 32];
    float d = v0 * a_w[64 + lane] + v1 * a_w[96 + lane];
    #pragma unroll
    for (int off = 16; off; off >>= 1) {
        s += __shfl_xor_sync(0xffffffffu, s, off);
        d += __shfl_xor_sync(0xffffffffu, d, off);
    }
    if (lane == 0) { g_src[row] = s; g_dst[row] = d; }
}

// ---------------------------------------------------------------------------
// Fused GAT attention per (b,h): softmax_j(leaky_relu(src_i + dst_j)) @ h.
// Factorized exp:  exp(LR(s+d)) = (s+d>=0) ? e^s * e^d : e^{0.2s} * e^{0.2d}
// ---------------------------------------------------------------------------
__global__ __launch_bounds__(256) void attn_kernel()
{
    const int bh  = blockIdx.y;          // 0..255
    const int i0  = blockIdx.x << 6;     // row-tile start
    const int tid = threadIdx.x;

    __shared__ float dstRaw[512], dstE1[512], dstE2[512];
    __shared__ float srcS[64];
    __shared__ float red[256];
    __shared__ float hT[64][64];

    const float* srcp = g_src + bh * Ssz;
    const float* dstp = g_dst + bh * Ssz;
    for (int u = tid; u < 512; u += 256) {
        const float dv = dstp[u];
        dstRaw[u] = dv;
        dstE1[u]  = __expf(dv);
        dstE2[u]  = __expf(NEG_SLOPE * dv);
    }
    if (tid < 64) srcS[tid] = srcp[i0 + tid];
    __syncthreads();

    const int r = tid >> 2, q = tid & 3;
    const float sv  = srcS[r];
    const float e1s = __expf(sv), e2s = __expf(NEG_SLOPE * sv);

    float ps = 0.f;
    #pragma unroll 4
    for (int jj = 0; jj < 128; jj++) {
        const int j = q + (jj << 2);
        const float d = dstRaw[j];
        ps += ((sv + d) >= 0.f) ? e1s * dstE1[j] : e2s * dstE2[j];
    }
    red[tid] = ps;
    __syncthreads();
    const float inv = 1.0f / (red[(r<<2)] + red[(r<<2)+1] + red[(r<<2)+2] + red[(r<<2)+3]);

    float acc[16];
    #pragma unroll
    for (int c = 0; c < 16; c++) acc[c] = 0.f;

    const float* hbase = g_h + (size_t)bh * Ssz * HDim;
    for (int jt = 0; jt < Ssz; jt += 64) {
        __syncthreads();
        #pragma unroll
        for (int u = 0; u < 4; u++) {
            const int v  = tid + (u << 8);
            const int jr = v >> 4;
            const int cc = (v & 15) << 2;
            *(float4*)&hT[jr][cc] = *(const float4*)&hbase[(size_t)(jt + jr) * HDim + cc];
        }
        __syncthreads();
        #pragma unroll 4
        for (int jj = 0; jj < 64; jj++) {
            const float d = dstRaw[jt + jj];
            const float w = (((sv + d) >= 0.f) ? e1s * dstE1[jt + jj]
                                               : e2s * dstE2[jt + jj]) * inv;
            #pragma unroll
            for (int k = 0; k < 4; k++) {
                const float4 hv = *(const float4*)&hT[jj][(q << 2) + (k << 4)];
                acc[k*4+0] = fmaf(w, hv.x, acc[k*4+0]);
                acc[k*4+1] = fmaf(w, hv.y, acc[k*4+1]);
                acc[k*4+2] = fmaf(w, hv.z, acc[k*4+2]);
                acc[k*4+3] = fmaf(w, hv.w, acc[k*4+3]);
            }
        }
    }

    float* outp = g_att + (size_t)(bh * Ssz + i0 + r) * HDim;
    #pragma unroll
    for (int k = 0; k < 4; k++)
        *(float4*)&outp[(q << 2) + (k << 4)] =
            make_float4(acc[k*4+0], acc[k*4+1], acc[k*4+2], acc[k*4+3]);
}

// ---------------------------------------------------------------------------
// LayerNorms (block per row of 512; thread handles d = tid, tid+256)
// ---------------------------------------------------------------------------
__device__ __forceinline__ void block_meanvar(float v0, float v1, int tid,
                                              float& mean, float& rstd)
{
    float s1 = v0 + v1;
    float s2 = v0 * v0 + v1 * v1;
    #pragma unroll
    for (int off = 16; off; off >>= 1) {
        s1 += __shfl_xor_sync(0xffffffffu, s1, off);
        s2 += __shfl_xor_sync(0xffffffffu, s2, off);
    }
    __shared__ float rs[8], rq[8];
    __shared__ float mn_s, rstd_s;
    const int lane = tid & 31, w = tid >> 5;
    if (lane == 0) { rs[w] = s1; rq[w] = s2; }
    __syncthreads();
    if (tid == 0) {
        float a = 0.f, c = 0.f;
        #pragma unroll
        for (int i = 0; i < 8; i++) { a += rs[i]; c += rq[i]; }
        const float m = a * (1.0f / 512.0f);
        const float var = c * (1.0f / 512.0f) - m * m;
        mn_s = m;
        rstd_s = rsqrtf(var + 1e-5f);
    }
    __syncthreads();
    mean = mn_s; rstd = rstd_s;
}

__global__ __launch_bounds__(256) void ln1_kernel(
    const float* __restrict__ x,
    const float* __restrict__ gw, const float* __restrict__ bw)
{
    const int m = blockIdx.x, tid = threadIdx.x;
    const int bb = m >> 9, s = m & 511;
    float v0, v1;
    {
        int d = tid;
        v0 = g_att[((((bb << 3) + (d >> 6)) << 9) + s) * HDim + (d & 63)]
           + x[(size_t)m * Dsz + d];
        d = tid + 256;
        v1 = g_att[((((bb << 3) + (d >> 6)) << 9) + s) * HDim + (d & 63)]
           + x[(size_t)m * Dsz + d];
    }
    float mean, rstd;
    block_meanvar(v0, v1, tid, mean, rstd);
    g_y[(size_t)m * Dsz + tid]       = (v0 - mean) * rstd * gw[tid]       + bw[tid];
    g_y[(size_t)m * Dsz + tid + 256] = (v1 - mean) * rstd * gw[tid + 256] + bw[tid + 256];
}

__global__ __launch_bounds__(256) void ln2_kernel(
    const float* __restrict__ gw, const float* __restrict__ bw,
    float* __restrict__ out)
{
    const int m = blockIdx.x, tid = threadIdx.x;
    const float v0 = g_pre2[(size_t)m * Dsz + tid];
    const float v1 = g_pre2[(size_t)m * Dsz + tid + 256];
    float mean, rstd;
    block_meanvar(v0, v1, tid, mean, rstd);
    out[(size_t)m * Dsz + tid]       = (v0 - mean) * rstd * gw[tid]       + bw[tid];
    out[(size_t)m * Dsz + tid + 256] = (v1 - mean) * rstd * gw[tid + 256] + bw[tid + 256];
}

// ---------------------------------------------------------------------------
// Launch. Input order: x, adj, w_W, w_b, a_w, sem_W, sem_b, ff1_W, ff1_b,
//                      ff2_W, ff2_b, ln1_g, ln1_b, ln2_g, ln2_b
// adj/sem_W/sem_b are provably dead (softmax output can never be exactly 0,
// so the mask is the identity) and are not read.
// ---------------------------------------------------------------------------
extern "C" void kernel_launch(void* const* d_in, const int* in_sizes, int n_in,
                              void* d_out, int out_size)
{
    const float* x     = (const float*)d_in[0];
    const float* w_W   = (const float*)d_in[2];
    const float* w_b   = (const float*)d_in[3];
    const float* a_w   = (const float*)d_in[4];
    const float* ff1_W = (const float*)d_in[7];
    const float* ff1_b = (const float*)d_in[8];
    const float* ff2_W = (const float*)d_in[9];
    const float* ff2_b = (const float*)d_in[10];
    const float* ln1_g = (const float*)d_in[11];
    const float* ln1_b = (const float*)d_in[12];
    const float* ln2_g = (const float*)d_in[13];
    const float* ln2_b = (const float*)d_in[14];
    float* out = (float*)d_out;

    static int configured = 0;
    if (!configured) {
        cudaFuncSetAttribute(mm_mma<1>, cudaFuncAttributeMaxDynamicSharedMemorySize, MM_SMEM_BYTES);
        cudaFuncSetAttribute(mm_mma<2>, cudaFuncAttributeMaxDynamicSharedMemorySize, MM_SMEM_BYTES);
        cudaFuncSetAttribute(mm_mma<3>, cudaFuncAttributeMaxDynamicSharedMemorySize, MM_SMEM_BYTES);
        configured = 1;
    }

    // 1) h = x @ w_W^T + w_b  -> g_h (B,H,S,HD)   [tf32 mma.sync]
    mm_mma<1><<<dim3(Dsz/128, Mrows/128), 256, MM_SMEM_BYTES>>>(x, w_W, w_b, Dsz, Dsz);
    // 2) src/dst projections
    src_dst_kernel<<<(Bsz*Hh*Ssz)/4, 128>>>(a_w);
    // 3) fused GAT attention -> g_att
    attn_kernel<<<dim3(Ssz/64, Bsz*Hh), 256>>>();
    // 4) LN1(att + x) -> g_y
    ln1_kernel<<<Mrows, 256>>>(x, ln1_g, ln1_b);
    // 5) g_ff = GeLU(g_y @ ff1_W^T + ff1_b)       [tf32 mma.sync]
    mm_mma<2><<<dim3(2*Dsz/128, Mrows/128), 256, MM_SMEM_BYTES>>>(nullptr, ff1_W, ff1_b, 2*Dsz, Dsz);
    // 6) g_pre2 = g_ff @ ff2_W^T + ff2_b + g_y    [tf32 mma.sync]
    mm_mma<3><<<dim3(Dsz/128, Mrows/128), 256, MM_SMEM_BYTES>>>(nullptr, ff2_W, ff2_b, Dsz, 2*Dsz);
    // 7) LN2 -> out
    ln2_kernel<<<Mrows, 256>>>(ln2_g, ln2_b, out);
}

// round 8
// speedup vs baseline: 2.9277x; 1.9020x over previous
#include <cuda_runtime.h>
#include <cuda_fp16.h>
#include <math.h>
#include <stdint.h>

// Problem constants
#define Bsz 32
#define Ssz 512
#define Dsz 512
#define Hh  8
#define HDim 64
#define Mrows (Bsz*Ssz)          // 16384
#define NEG_SLOPE 0.2f

// ---------------------------------------------------------------------------
// Scratch (static __device__ arrays; allocation is forbidden)
// ---------------------------------------------------------------------------
__device__ float  g_h   [Bsz*Hh*Ssz*HDim];   // (B,H,S,HD) projected heads, fp32
__device__ __half g_hT  [Bsz*Hh*HDim*Ssz];   // (bh, d, s) fp16 transposed
__device__ float  g_src [Bsz*Hh*Ssz];
__device__ float  g_dst [Bsz*Hh*Ssz];
__device__ float  g_att [Bsz*Hh*Ssz*HDim];   // attention output, (B,H,S,HD)
__device__ float  g_y   [Mrows*Dsz];         // post-LN1 activations
__device__ float  g_ff  [Mrows*2*Dsz];       // GeLU(ff1) activations
__device__ float  g_pre2[Mrows*Dsz];         // ff2 out + residual (pre-LN2)

// ---------------------------------------------------------------------------
// helpers
// ---------------------------------------------------------------------------
__device__ __forceinline__ uint32_t pack2h(float x, float y) {
    __half2 h = __floats2half2_rn(x, y);
    return *reinterpret_cast<uint32_t*>(&h);
}
__device__ __forceinline__ void mma16(float* c, const uint32_t* a, const uint32_t* b) {
    asm volatile(
        "mma.sync.aligned.m16n8k16.row.col.f32.f16.f16.f32 "
        "{%0,%1,%2,%3}, {%4,%5,%6,%7}, {%8,%9}, {%0,%1,%2,%3};"
        : "+f"(c[0]), "+f"(c[1]), "+f"(c[2]), "+f"(c[3])
        : "r"(a[0]), "r"(a[1]), "r"(a[2]), "r"(a[3]), "r"(b[0]), "r"(b[1]));
}

// ---------------------------------------------------------------------------
// fp16 tensor-core GEMM: C = A @ W^T + bias (both row-major, K contiguous).
// CTA 128x128, BK=32, 256 threads (8 warps, warp tile 64x32), m16n8k16,
// double-buffered smem; LDK2=20 u32/row -> conflict-free frag LDS.
// EPI: 1 = write to g_h with (B,H,S,HD) scatter (A = param)
//      2 = exact GeLU, A = g_y, C = g_ff
//      3 = + residual g_y, A = g_ff, C = g_pre2
// ---------------------------------------------------------------------------
#define LDK2 20                    // u32 per smem row (32 halfs + 8 pad)
#define HSTG (128*LDK2)            // 2560 u32 per stage per matrix

template<int EPI>
__global__ __launch_bounds__(256, 1) void mm_mma(
    const float* __restrict__ Ain, const float* __restrict__ W,
    const float* __restrict__ bias, int N, int K)
{
    __shared__ uint32_t As[2][HSTG];
    __shared__ uint32_t Bs[2][HSTG];

    const float* A = (EPI == 1) ? Ain : (EPI == 2 ? (const float*)g_y
                                                  : (const float*)g_ff);

    const int tid  = threadIdx.x;
    const int wid  = tid >> 5;
    const int lane = tid & 31;
    const int g    = lane >> 2;
    const int t    = lane & 3;
    const int bm   = blockIdx.y << 7;
    const int bn   = blockIdx.x << 7;
    const int wm   = (wid & 1) << 6;   // 0/64
    const int wn   = (wid >> 1) << 5;  // 0/32/64/96

    float acc[4][4][4];
    #pragma unroll
    for (int mi = 0; mi < 4; mi++)
        #pragma unroll
        for (int ni = 0; ni < 4; ni++)
            #pragma unroll
            for (int c = 0; c < 4; c++) acc[mi][ni][c] = 0.f;

    float4 pa[4], pb[4];
    auto fetch = [&](int kt) {
        const int k0 = kt << 5;
        #pragma unroll
        for (int u = 0; u < 4; u++) {
            const int idx = tid + (u << 8);
            const int r = idx >> 3, c4 = idx & 7;
            pa[u] = *(const float4*)(A + (size_t)(bm + r) * K + k0 + (c4 << 2));
            pb[u] = *(const float4*)(W + (size_t)(bn + r) * K + k0 + (c4 << 2));
        }
    };
    auto stage = [&](int buf) {
        uint32_t* Ad = As[buf];
        uint32_t* Bd = Bs[buf];
        #pragma unroll
        for (int u = 0; u < 4; u++) {
            const int idx = tid + (u << 8);
            const int r = idx >> 3, c4 = idx & 7;
            const int o = r * LDK2 + (c4 << 1);
            *(uint2*)(Ad + o) = make_uint2(pack2h(pa[u].x, pa[u].y),
                                           pack2h(pa[u].z, pa[u].w));
            *(uint2*)(Bd + o) = make_uint2(pack2h(pb[u].x, pb[u].y),
                                           pack2h(pb[u].z, pb[u].w));
        }
    };

    const int nkt = K >> 5;
    fetch(0);
    stage(0);
    __syncthreads();

    int buf = 0;
    for (int kt = 0; kt < nkt; kt++) {
        if (kt + 1 < nkt) fetch(kt + 1);

        const uint32_t* Ab = As[buf];
        const uint32_t* Bb = Bs[buf];
        #pragma unroll
        for (int kc = 0; kc < 2; kc++) {       // two k16 chunks in BK=32
            uint32_t af[4][4], bf[4][2];
            #pragma unroll
            for (int mi = 0; mi < 4; mi++) {
                const uint32_t* p = Ab + (wm + (mi << 4) + g) * LDK2 + (kc << 3) + t;
                af[mi][0] = p[0];
                af[mi][1] = p[8 * LDK2];
                af[mi][2] = p[4];
                af[mi][3] = p[8 * LDK2 + 4];
            }
            #pragma unroll
            for (int ni = 0; ni < 4; ni++) {
                const uint32_t* p = Bb + (wn + (ni << 3) + g) * LDK2 + (kc << 3) + t;
                bf[ni][0] = p[0];
                bf[ni][1] = p[4];
            }
            #pragma unroll
            for (int mi = 0; mi < 4; mi++)
                #pragma unroll
                for (int ni = 0; ni < 4; ni++)
                    mma16(acc[mi][ni], af[mi], bf[ni]);
        }

        if (kt + 1 < nkt) {
            buf ^= 1;
            stage(buf);
            __syncthreads();
        }
    }

    // ---------------- epilogue ----------------
    #pragma unroll
    for (int ni = 0; ni < 4; ni++) {
        const int col = bn + wn + (ni << 3) + (t << 1);
        const float2 bb = *(const float2*)&bias[col];
        #pragma unroll
        for (int mi = 0; mi < 4; mi++) {
            #pragma unroll
            for (int half = 0; half < 2; half++) {
                const int row = bm + wm + (mi << 4) + g + (half << 3);
                float2 v;
                v.x = acc[mi][ni][half*2+0] + bb.x;
                v.y = acc[mi][ni][half*2+1] + bb.y;
                if (EPI == 2) {
                    v.x = 0.5f*v.x*(1.f + erff(v.x*0.70710678118654752f));
                    v.y = 0.5f*v.y*(1.f + erff(v.y*0.70710678118654752f));
                }
                if (EPI == 3) {
                    const float2 rr = *(const float2*)&g_y[(size_t)row * Dsz + col];
                    v.x += rr.x; v.y += rr.y;
                }
                if (EPI == 1) {
                    const int bI = row >> 9, sI = row & 511;
                    const int hh = col >> 6, hd = col & 63;
                    *(float2*)&g_h[((size_t)(((bI << 3) + hh) << 9) + sI) * HDim + hd] = v;
                } else if (EPI == 2) {
                    *(float2*)&g_ff[(size_t)row * N + col] = v;
                } else {
                    *(float2*)&g_pre2[(size_t)row * Dsz + col] = v;
                }
            }
        }
    }
}

// ---------------------------------------------------------------------------
// h transpose: g_h (bh, s, d) fp32 -> g_hT (bh, d, s) fp16, 64x64 smem tiles.
// Each thread stores 2 x uint4 covering s offsets {p*8, p*8+32} -> full 0..63.
// ---------------------------------------------------------------------------
__global__ __launch_bounds__(256) void h2t_kernel()
{
    __shared__ float tbuf[64][65];
    const int bh = blockIdx.y;
    const int s0 = blockIdx.x << 6;
    const int tid = threadIdx.x;
    const float* hp = g_h + (size_t)bh * Ssz * HDim;
    #pragma unroll
    for (int u = 0; u < 4; u++) {
        const int idx = tid + (u << 8);
        const int r = idx >> 4, c4 = (idx & 15) << 2;
        float4 v = *(const float4*)(hp + (size_t)(s0 + r) * HDim + c4);
        tbuf[r][c4+0] = v.x; tbuf[r][c4+1] = v.y;
        tbuf[r][c4+2] = v.z; tbuf[r][c4+3] = v.w;
    }
    __syncthreads();
    const int d = tid >> 2, p = tid & 3;
    #pragma unroll
    for (int u = 0; u < 2; u++) {
        const int sofs = (p << 3) + (u << 5);     // 0..31 + {0, 32}
        __half hv[8];
        #pragma unroll
        for (int k = 0; k < 8; k++)
            hv[k] = __float2half(tbuf[sofs + k][d]);
        *(uint4*)((__half*)g_hT + ((size_t)bh * HDim + d) * Ssz + s0 + sofs) =
            *(uint4*)hv;
    }
}

// ---------------------------------------------------------------------------
// src/dst projections: one warp per (b,h,s) row of h
// ---------------------------------------------------------------------------
__global__ __launch_bounds__(128) void src_dst_kernel(const float* __restrict__ a_w)
{
    const int row  = blockIdx.x * 4 + (threadIdx.x >> 5);
    const int lane = threadIdx.x & 31;
    const float* hrow = g_h + (size_t)row * HDim;
    const float v0 = hrow[lane], v1 = hrow[lane + 32];
    float s = v0 * a_w[lane]      + v1 * a_w[lane + 32];
    float d = v0 * a_w[64 + lane] + v1 * a_w[96 + lane];
    #pragma unroll
    for (int off = 16; off; off >>= 1) {
        s += __shfl_xor_sync(0xffffffffu, s, off);
        d += __shfl_xor_sync(0xffffffffu, d, off);
    }
    if (lane == 0) { g_src[row] = s; g_dst[row] = d; }
}

// ---------------------------------------------------------------------------
// Fused GAT attention with tensor-core AV.
// Per CTA: (b,h) and a 128-row i-tile. Factorized exp:
//   P[i][j] = (s_i+d_j>=0) ? e^{s_i}e^{d_j}/Z_i : e^{.2 s_i}e^{.2 d_j}/Z_i
// P computed to fp16 smem in 128x128 j-tiles; AV = P @ H via m16n8k16 with
// H staged fp16-transposed from g_hT. fp32 accum; out to g_att.
// ---------------------------------------------------------------------------
#define ATT_P_OFF   0
#define ATT_HS_OFF  (128*68)                 // 8704
#define ATT_F_OFF   (ATT_HS_OFF + 64*68)     // 13056
#define ATT_SMEM_U32 (ATT_F_OFF + 512*3 + 128 + 256)
#define ATT_SMEM_BYTES (ATT_SMEM_U32*4)      // 59904

__global__ __launch_bounds__(256, 1) void attn_mma_kernel()
{
    extern __shared__ uint32_t sm[];
    uint32_t* P  = sm + ATT_P_OFF;
    uint32_t* Hs = sm + ATT_HS_OFF;
    float* dstRaw = (float*)(sm + ATT_F_OFF);
    float* dstE1  = dstRaw + 512;
    float* dstE2  = dstE1 + 512;
    float* srcS   = dstE2 + 512;   // 128
    float* red    = srcS + 128;    // 256

    const int bh  = blockIdx.y;
    const int i0  = blockIdx.x << 7;
    const int tid = threadIdx.x;
    const int wid = tid >> 5, lane = tid & 31;
    const int g = lane >> 2, t = lane & 3;
    const int wm = (wid & 3) << 5;   // warp i-offset (0..96)
    const int wn = (wid >> 2) << 5;  // warp d-offset (0/32)

    const float* dstp = g_dst + bh * Ssz;
    for (int u = tid; u < 512; u += 256) {
        const float dv = dstp[u];
        dstRaw[u] = dv;
        dstE1[u]  = __expf(dv);
        dstE2[u]  = __expf(NEG_SLOPE * dv);
    }
    if (tid < 128) srcS[tid] = g_src[bh * Ssz + i0 + tid];
    __syncthreads();

    // denominator: 2 threads per row, 256 j's each
    {
        const int r = tid >> 1, q2 = tid & 1;
        const float sv = srcS[r];
        const float e1 = __expf(sv), e2 = __expf(NEG_SLOPE * sv);
        float ps = 0.f;
        #pragma unroll 4
        for (int jj = 0; jj < 256; jj++) {
            const int j = (q2 << 8) + jj;
            const float d = dstRaw[j];
            ps += ((sv + d) >= 0.f) ? e1 * dstE1[j] : e2 * dstE2[j];
        }
        red[tid] = ps;
    }
    __syncthreads();

    // per-thread P-generation params (row ip)
    const int ip = tid & 127, qp = tid >> 7;
    const float svi = srcS[ip];
    const float invD = 1.0f / (red[2*ip] + red[2*ip + 1]);
    const float a1 = __expf(svi) * invD;
    const float a2 = __expf(NEG_SLOPE * svi) * invD;

    float acc[2][4][4];
    #pragma unroll
    for (int mi = 0; mi < 2; mi++)
        #pragma unroll
        for (int ni = 0; ni < 4; ni++)
            #pragma unroll
            for (int c = 0; c < 4; c++) acc[mi][ni][c] = 0.f;

    const __half* hT = (const __half*)g_hT + (size_t)bh * HDim * Ssz;

    for (int jt = 0; jt < 4; jt++) {
        __syncthreads();                       // protect prev tile from rewrite
        // ---- P tile: thread fills row ip, 64 halfs starting at qp*64 ----
        {
            uint32_t* Pd = P + ip * 68 + (qp << 5);
            const int jb = (jt << 7) + (qp << 6);
            #pragma unroll
            for (int c8 = 0; c8 < 8; c8++) {
                float v[8];
                #pragma unroll
                for (int k = 0; k < 8; k++) {
                    const int j = jb + (c8 << 3) + k;
                    const float d = dstRaw[j];
                    v[k] = ((svi + d) >= 0.f) ? a1 * dstE1[j] : a2 * dstE2[j];
                }
                uint4 pk;
                pk.x = pack2h(v[0], v[1]); pk.y = pack2h(v[2], v[3]);
                pk.z = pack2h(v[4], v[5]); pk.w = pack2h(v[6], v[7]);
                *(uint4*)(Pd + (c8 << 2)) = pk;
            }
        }
        // ---- Hs tile: 64 d-rows x 128 halfs from g_hT ----
        {
            const int d = tid >> 2, p = tid & 3;
            const __half* src = hT + (size_t)d * Ssz + (jt << 7) + (p << 5);
            #pragma unroll
            for (int u = 0; u < 4; u++) {
                uint4 val = *(const uint4*)(src + (u << 3));   // 8 halfs
                *(uint4*)(Hs + d * 68 + (p << 4) + (u << 2)) = val;
            }
        }
        __syncthreads();
        // ---- mma over 8 k16 chunks ----
        #pragma unroll
        for (int ch = 0; ch < 8; ch++) {
            uint32_t af[2][4], bf[4][2];
            #pragma unroll
            for (int mi = 0; mi < 2; mi++) {
                const uint32_t* p = P + (wm + (mi << 4) + g) * 68 + (ch << 3) + t;
                af[mi][0] = p[0];
                af[mi][1] = p[8 * 68];
                af[mi][2] = p[4];
                af[mi][3] = p[8 * 68 + 4];
            }
            #pragma unroll
            for (int ni = 0; ni < 4; ni++) {
                const uint32_t* p = Hs + (wn + (ni << 3) + g) * 68 + (ch << 3) + t;
                bf[ni][0] = p[0];
                bf[ni][1] = p[4];
            }
            #pragma unroll
            for (int mi = 0; mi < 2; mi++)
                #pragma unroll
                for (int ni = 0; ni < 4; ni++)
                    mma16(acc[mi][ni], af[mi], bf[ni]);
        }
    }

    // ---- epilogue: acc -> g_att (bh, s, d) fp32 ----
    #pragma unroll
    for (int mi = 0; mi < 2; mi++) {
        #pragma unroll
        for (int half = 0; half < 2; half++) {
            const int row = i0 + wm + (mi << 4) + g + (half << 3);
            float* op = g_att + ((size_t)bh * Ssz + row) * HDim;
            #pragma unroll
            for (int ni = 0; ni < 4; ni++) {
                const int col = wn + (ni << 3) + (t << 1);
                *(float2*)(op + col) =
                    make_float2(acc[mi][ni][half*2], acc[mi][ni][half*2+1]);
            }
        }
    }
}

// ---------------------------------------------------------------------------
// LayerNorms (block per row of 512; thread handles d = tid, tid+256)
// ---------------------------------------------------------------------------
__device__ __forceinline__ void block_meanvar(float v0, float v1, int tid,
                                              float& mean, float& rstd)
{
    float s1 = v0 + v1;
    float s2 = v0 * v0 + v1 * v1;
    #pragma unroll
    for (int off = 16; off; off >>= 1) {
        s1 += __shfl_xor_sync(0xffffffffu, s1, off);
        s2 += __shfl_xor_sync(0xffffffffu, s2, off);
    }
    __shared__ float rs[8], rq[8];
    __shared__ float mn_s, rstd_s;
    const int lane = tid & 31, w = tid >> 5;
    if (lane == 0) { rs[w] = s1; rq[w] = s2; }
    __syncthreads();
    if (tid == 0) {
        float a = 0.f, c = 0.f;
        #pragma unroll
        for (int i = 0; i < 8; i++) { a += rs[i]; c += rq[i]; }
        const float m = a * (1.0f / 512.0f);
        const float var = c * (1.0f / 512.0f) - m * m;
        mn_s = m;
        rstd_s = rsqrtf(var + 1e-5f);
    }
    __syncthreads();
    mean = mn_s; rstd = rstd_s;
}

__global__ __launch_bounds__(256) void ln1_kernel(
    const float* __restrict__ x,
    const float* __restrict__ gw, const float* __restrict__ bw)
{
    const int m = blockIdx.x, tid = threadIdx.x;
    const int bb = m >> 9, s = m & 511;
    float v0, v1;
    {
        int d = tid;
        v0 = g_att[((((bb << 3) + (d >> 6)) << 9) + s) * HDim + (d & 63)]
           + x[(size_t)m * Dsz + d];
        d = tid + 256;
        v1 = g_att[((((bb << 3) + (d >> 6)) << 9) + s) * HDim + (d & 63)]
           + x[(size_t)m * Dsz + d];
    }
    float mean, rstd;
    block_meanvar(v0, v1, tid, mean, rstd);
    g_y[(size_t)m * Dsz + tid]       = (v0 - mean) * rstd * gw[tid]       + bw[tid];
    g_y[(size_t)m * Dsz + tid + 256] = (v1 - mean) * rstd * gw[tid + 256] + bw[tid + 256];
}

__global__ __launch_bounds__(256) void ln2_kernel(
    const float* __restrict__ gw, const float* __restrict__ bw,
    float* __restrict__ out)
{
    const int m = blockIdx.x, tid = threadIdx.x;
    const float v0 = g_pre2[(size_t)m * Dsz + tid];
    const float v1 = g_pre2[(size_t)m * Dsz + tid + 256];
    float mean, rstd;
    block_meanvar(v0, v1, tid, mean, rstd);
    out[(size_t)m * Dsz + tid]       = (v0 - mean) * rstd * gw[tid]       + bw[tid];
    out[(size_t)m * Dsz + tid + 256] = (v1 - mean) * rstd * gw[tid + 256] + bw[tid + 256];
}

// ---------------------------------------------------------------------------
// Launch. Input order: x, adj, w_W, w_b, a_w, sem_W, sem_b, ff1_W, ff1_b,
//                      ff2_W, ff2_b, ln1_g, ln1_b, ln2_g, ln2_b
// adj/sem_W/sem_b are provably dead (softmax output can never be exactly 0,
// so the mask is the identity) and are not read.
// ---------------------------------------------------------------------------
extern "C" void kernel_launch(void* const* d_in, const int* in_sizes, int n_in,
                              void* d_out, int out_size)
{
    const float* x     = (const float*)d_in[0];
    const float* w_W   = (const float*)d_in[2];
    const float* w_b   = (const float*)d_in[3];
    const float* a_w   = (const float*)d_in[4];
    const float* ff1_W = (const float*)d_in[7];
    const float* ff1_b = (const float*)d_in[8];
    const float* ff2_W = (const float*)d_in[9];
    const float* ff2_b = (const float*)d_in[10];
    const float* ln1_g = (const float*)d_in[11];
    const float* ln1_b = (const float*)d_in[12];
    const float* ln2_g = (const float*)d_in[13];
    const float* ln2_b = (const float*)d_in[14];
    float* out = (float*)d_out;

    cudaFuncSetAttribute(attn_mma_kernel,
                         cudaFuncAttributeMaxDynamicSharedMemorySize,
                         ATT_SMEM_BYTES);

    // 1) h = x @ w_W^T + w_b  -> g_h (B,H,S,HD)   [fp16 mma]
    mm_mma<1><<<dim3(Dsz/128, Mrows/128), 256>>>(x, w_W, w_b, Dsz, Dsz);
    // 2) transpose h to fp16 (bh, d, s)
    h2t_kernel<<<dim3(Ssz/64, Bsz*Hh), 256>>>();
    // 3) src/dst projections
    src_dst_kernel<<<(Bsz*Hh*Ssz)/4, 128>>>(a_w);
    // 4) fused GAT attention (tensor-core AV) -> g_att
    attn_mma_kernel<<<dim3(Ssz/128, Bsz*Hh), 256, ATT_SMEM_BYTES>>>();
    // 5) LN1(att + x) -> g_y
    ln1_kernel<<<Mrows, 256>>>(x, ln1_g, ln1_b);
    // 6) g_ff = GeLU(g_y @ ff1_W^T + ff1_b)       [fp16 mma]
    mm_mma<2><<<dim3(2*Dsz/128, Mrows/128), 256>>>(nullptr, ff1_W, ff1_b, 2*Dsz, Dsz);
    // 7) g_pre2 = g_ff @ ff2_W^T + ff2_b + g_y    [fp16 mma]
    mm_mma<3><<<dim3(Dsz/128, Mrows/128), 256>>>(nullptr, ff2_W, ff2_b, Dsz, 2*Dsz);
    // 8) LN2 -> out
    ln2_kernel<<<Mrows, 256>>>(ln2_g, ln2_b, out);
}

// round 10
// speedup vs baseline: 3.6560x; 1.2488x over previous
#include <cuda_runtime.h>
#include <cuda_fp16.h>
#include <math.h>
#include <stdint.h>

// Problem constants
#define Bsz 32
#define Ssz 512
#define Dsz 512
#define Hh  8
#define HDim 64
#define Mrows (Bsz*Ssz)          // 16384
#define NEG_SLOPE 0.2f

// ---------------------------------------------------------------------------
// Scratch (static __device__ arrays; allocation is forbidden)
// ---------------------------------------------------------------------------
__device__ __half g_x16 [Mrows*Dsz];         // x in fp16
__device__ __half g_w16 [Dsz*Dsz];           // w_W fp16
__device__ __half g_f1w16[2*Dsz*Dsz];        // ff1_W fp16
__device__ __half g_f2w16[2*Dsz*Dsz];        // ff2_W fp16
__device__ __half g_h16 [Bsz*Hh*Ssz*HDim];   // (bh,s,hd) projected heads fp16
__device__ __half g_hT  [Bsz*Hh*HDim*Ssz];   // (bh, d, s) fp16 transposed
__device__ float  g_src [Bsz*Hh*Ssz];
__device__ float  g_dst [Bsz*Hh*Ssz];
__device__ float  g_att [Bsz*Hh*Ssz*HDim];   // attention output fp32
__device__ float  g_y   [Mrows*Dsz];         // post-LN1 fp32 (residual for EPI3)
__device__ __half g_y16 [Mrows*Dsz];         // post-LN1 fp16 (mm2 input)
__device__ __half g_ff16[Mrows*2*Dsz];       // GeLU(ff1) fp16 (mm3 input)
__device__ float  g_pre2[Mrows*Dsz];         // ff2 out + residual (pre-LN2)

// ---------------------------------------------------------------------------
// helpers
// ---------------------------------------------------------------------------
__device__ __forceinline__ uint32_t pack2h(float x, float y) {
    __half2 h = __floats2half2_rn(x, y);
    return *reinterpret_cast<uint32_t*>(&h);
}
__device__ __forceinline__ uint32_t sm32(const void* p) {
    return (uint32_t)__cvta_generic_to_shared(p);
}
__device__ __forceinline__ void mma16(float* c, const uint32_t* a, const uint32_t* b) {
    asm volatile(
        "mma.sync.aligned.m16n8k16.row.col.f32.f16.f16.f32 "
        "{%0,%1,%2,%3}, {%4,%5,%6,%7}, {%8,%9}, {%0,%1,%2,%3};"
        : "+f"(c[0]), "+f"(c[1]), "+f"(c[2]), "+f"(c[3])
        : "r"(a[0]), "r"(a[1]), "r"(a[2]), "r"(a[3]), "r"(b[0]), "r"(b[1]));
}
#define CP16(sa, ga) asm volatile("cp.async.cg.shared.global [%0], [%1], 16;" :: "r"(sa), "l"(ga))
#define CPCOMMIT()   asm volatile("cp.async.commit_group;" ::: "memory")
#define CPWAIT1()    asm volatile("cp.async.wait_group 1;" ::: "memory")

// ---------------------------------------------------------------------------
// fp32 -> fp16 conversion (x and the three weight matrices), n % 1024 == 0
// ---------------------------------------------------------------------------
__global__ __launch_bounds__(256) void f2h_kernel(
    const float* __restrict__ s, __half* __restrict__ d, int n)
{
    const int i = (blockIdx.x * 256 + threadIdx.x) * 4;
    if (i < n) {
        float4 v = *(const float4*)(s + i);
        *(uint2*)(d + i) = make_uint2(pack2h(v.x, v.y), pack2h(v.z, v.w));
    }
}

// ---------------------------------------------------------------------------
// fp16 tensor-core GEMM: C = A @ W^T + bias. A (M,K) fp16 row-major,
// W (N,K) fp16 row-major. CTA 128x128, BK=32, 256 threads (8 warps, warp
// tile 64x32), m16n8k16, 3-stage cp.async pipeline. LDKu=20 u32/row pad.
// EPI: 1 = + w_b -> g_h16 (bh,s,hd) scatter fp16
//      2 = GeLU  -> g_ff16 fp16
//      3 = + residual g_y -> g_pre2 fp32
// ---------------------------------------------------------------------------
#define LDKu 20
#define MSTG (128*LDKu)            // 2560 u32 per stage per matrix
#define MM_SMEM (3*MSTG*4*2)       // 61440 B

template<int EPI>
__global__ __launch_bounds__(256, 1) void mm_mma(
    const __half* __restrict__ A, const __half* __restrict__ W,
    const float* __restrict__ bias, int N, int K)
{
    extern __shared__ uint32_t smm[];
    uint32_t* As = smm;                 // [3][MSTG]
    uint32_t* Bs = smm + 3*MSTG;        // [3][MSTG]

    const int tid  = threadIdx.x;
    const int wid  = tid >> 5;
    const int lane = tid & 31;
    const int g    = lane >> 2;
    const int t    = lane & 3;
    const int bm   = blockIdx.y << 7;
    const int bn   = blockIdx.x << 7;
    const int wm   = (wid & 1) << 6;   // 0/64
    const int wn   = (wid >> 1) << 5;  // 0/32/64/96

    float acc[4][4][4];
    #pragma unroll
    for (int mi = 0; mi < 4; mi++)
        #pragma unroll
        for (int ni = 0; ni < 4; ni++)
            #pragma unroll
            for (int c = 0; c < 4; c++) acc[mi][ni][c] = 0.f;

    // producer: 512 16B-chunks per matrix per stage; 2 per thread
    auto issue = [&](int kt, int slot) {
        const int k0 = kt << 5;
        #pragma unroll
        for (int u = 0; u < 2; u++) {
            const int idx = tid + (u << 8);
            const int r = idx >> 2, c = idx & 3;
            const __half* ga = A + (size_t)(bm + r) * K + k0 + (c << 3);
            const __half* gb = W + (size_t)(bn + r) * K + k0 + (c << 3);
            CP16(sm32(As + slot*MSTG + r*LDKu + (c << 2)), ga);
            CP16(sm32(Bs + slot*MSTG + r*LDKu + (c << 2)), gb);
        }
        CPCOMMIT();
    };

    const int nkt = K >> 5;
    issue(0, 0);
    issue(1, 1);

    for (int kt = 0; kt < nkt; kt++) {
        CPWAIT1();                 // stage kt complete
        __syncthreads();
        if (kt + 2 < nkt) issue(kt + 2, (kt + 2) % 3);

        const uint32_t* Ab = As + (kt % 3) * MSTG;
        const uint32_t* Bb = Bs + (kt % 3) * MSTG;
        #pragma unroll
        for (int kc = 0; kc < 2; kc++) {
            uint32_t af[4][4], bf[4][2];
            #pragma unroll
            for (int mi = 0; mi < 4; mi++) {
                const uint32_t* p = Ab + (wm + (mi << 4) + g) * LDKu + (kc << 3) + t;
                af[mi][0] = p[0];
                af[mi][1] = p[8 * LDKu];
                af[mi][2] = p[4];
                af[mi][3] = p[8 * LDKu + 4];
            }
            #pragma unroll
            for (int ni = 0; ni < 4; ni++) {
                const uint32_t* p = Bb + (wn + (ni << 3) + g) * LDKu + (kc << 3) + t;
                bf[ni][0] = p[0];
                bf[ni][1] = p[4];
            }
            #pragma unroll
            for (int mi = 0; mi < 4; mi++)
                #pragma unroll
                for (int ni = 0; ni < 4; ni++)
                    mma16(acc[mi][ni], af[mi], bf[ni]);
        }
    }

    // ---------------- epilogue ----------------
    #pragma unroll
    for (int ni = 0; ni < 4; ni++) {
        const int col = bn + wn + (ni << 3) + (t << 1);
        const float2 bb = *(const float2*)&bias[col];
        #pragma unroll
        for (int mi = 0; mi < 4; mi++) {
            #pragma unroll
            for (int half = 0; half < 2; half++) {
                const int row = bm + wm + (mi << 4) + g + (half << 3);
                float2 v;
                v.x = acc[mi][ni][half*2+0] + bb.x;
                v.y = acc[mi][ni][half*2+1] + bb.y;
                if (EPI == 2) {
                    v.x = 0.5f*v.x*(1.f + erff(v.x*0.70710678118654752f));
                    v.y = 0.5f*v.y*(1.f + erff(v.y*0.70710678118654752f));
                }
                if (EPI == 3) {
                    const float2 rr = *(const float2*)&g_y[(size_t)row * Dsz + col];
                    v.x += rr.x; v.y += rr.y;
                }
                if (EPI == 1) {        // scatter fp16 to (bh, s, hd)
                    const int bI = row >> 9, sI = row & 511;
                    const int hh = col >> 6, hd = col & 63;
                    *(uint32_t*)&g_h16[((size_t)(((bI << 3) + hh) << 9) + sI) * HDim + hd] =
                        pack2h(v.x, v.y);
                } else if (EPI == 2) {
                    *(uint32_t*)&g_ff16[(size_t)row * N + col] = pack2h(v.x, v.y);
                } else {
                    *(float2*)&g_pre2[(size_t)row * Dsz + col] = v;
                }
            }
        }
    }
}

// ---------------------------------------------------------------------------
// h transpose: g_h16 (bh,s,d) -> g_hT (bh,d,s), 64x64 fp16 smem tiles.
// tile row stride 72 halfs (16B-aligned, conflict-free with d=tid&63 reads).
// ---------------------------------------------------------------------------
__global__ __launch_bounds__(256) void h2t_kernel()
{
    __shared__ __half tbuf[64][72];
    const int bh = blockIdx.y;
    const int s0 = blockIdx.x << 6;
    const int tid = threadIdx.x;
    const __half* hp = g_h16 + (size_t)bh * Ssz * HDim;
    #pragma unroll
    for (int u = 0; u < 2; u++) {
        const int idx = tid + (u << 8);
        const int r = idx >> 3, c8 = idx & 7;
        *(uint4*)&tbuf[r][c8 << 3] =
            *(const uint4*)(hp + (size_t)(s0 + r) * HDim + (c8 << 3));
    }
    __syncthreads();
    const int d = tid & 63, pr = tid >> 6;
    #pragma unroll
    for (int u = 0; u < 2; u++) {
        const int sofs = (pr << 3) + (u << 5);    // covers 0..63 across pr,u
        __half hv[8];
        #pragma unroll
        for (int k = 0; k < 8; k++)
            hv[k] = tbuf[sofs + k][d];
        *(uint4*)(g_hT + ((size_t)bh * HDim + d) * Ssz + s0 + sofs) = *(uint4*)hv;
    }
}

// ---------------------------------------------------------------------------
// src/dst projections: one warp per (b,h,s) row of g_h16
// ---------------------------------------------------------------------------
__global__ __launch_bounds__(128) void src_dst_kernel(const float* __restrict__ a_w)
{
    const int row  = blockIdx.x * 4 + (threadIdx.x >> 5);
    const int lane = threadIdx.x & 31;
    const __half* hrow = g_h16 + (size_t)row * HDim;
    const float v0 = __half2float(hrow[lane]);
    const float v1 = __half2float(hrow[lane + 32]);
    float s = v0 * a_w[lane]      + v1 * a_w[lane + 32];
    float d = v0 * a_w[64 + lane] + v1 * a_w[96 + lane];
    #pragma unroll
    for (int off = 16; off; off >>= 1) {
        s += __shfl_xor_sync(0xffffffffu, s, off);
        d += __shfl_xor_sync(0xffffffffu, d, off);
    }
    if (lane == 0) { g_src[row] = s; g_dst[row] = d; }
}

// ---------------------------------------------------------------------------
// Fused GAT attention, tensor-core AV, P generated DIRECTLY in mma A-fragment
// registers (no P smem). Factorized exp:
//   P[i][j] = (d_j >= -s_i) ? e^{s_i}E1[j]/Z_i : e^{.2 s_i}E2[j]/Z_i
// A-frag (m16n8k16): a0=(rA, j0,j0+1) a1=(rB, ..) a2=(rA, j0+8,j0+9) a3=(rB,..)
// with rA = wm+mi*16+g, rB = rA+8, j0 = jt*128 + ch*16 + 2t.
// ---------------------------------------------------------------------------
__global__ __launch_bounds__(256, 1) void attn_mma_kernel()
{
    __shared__ float4  dstP[512];          // {raw, e^d, e^{0.2d}, 0}
    __shared__ float   srcS[128];
    __shared__ float   red [256];
    __shared__ uint32_t Hs [64*68];

    const int bh  = blockIdx.y;
    const int i0  = blockIdx.x << 7;
    const int tid = threadIdx.x;
    const int wid = tid >> 5, lane = tid & 31;
    const int g = lane >> 2, t = lane & 3;
    const int wm = (wid & 3) << 5;   // warp i-offset
    const int wn = (wid >> 2) << 5;  // warp d-offset

    const float* dstp = g_dst + bh * Ssz;
    for (int u = tid; u < 512; u += 256) {
        const float dv = dstp[u];
        dstP[u] = make_float4(dv, __expf(dv), __expf(NEG_SLOPE * dv), 0.f);
    }
    if (tid < 128) srcS[tid] = g_src[bh * Ssz + i0 + tid];
    __syncthreads();

    // denominator: 2 threads per row
    {
        const int r = tid >> 1, q2 = tid & 1;
        const float sv = srcS[r];
        const float e1 = __expf(sv), e2 = __expf(NEG_SLOPE * sv);
        float ps = 0.f;
        #pragma unroll 4
        for (int jj = 0; jj < 256; jj++) {
            const float4 dp = dstP[(q2 << 8) + jj];
            ps += ((sv + dp.x) >= 0.f) ? e1 * dp.y : e2 * dp.z;
        }
        red[tid] = ps;
    }
    __syncthreads();

    // per-thread row constants for rows wm + q*8 + g (q = mi*2 + half)
    float thr[4], a1c[4], a2c[4];
    #pragma unroll
    for (int q = 0; q < 4; q++) {
        const int rr = wm + (q << 3) + g;
        const float sv = srcS[rr];
        const float invD = 1.0f / (red[2*rr] + red[2*rr + 1]);
        thr[q] = -sv;
        a1c[q] = __expf(sv) * invD;
        a2c[q] = __expf(NEG_SLOPE * sv) * invD;
    }

    float acc[2][4][4];
    #pragma unroll
    for (int mi = 0; mi < 2; mi++)
        #pragma unroll
        for (int ni = 0; ni < 4; ni++)
            #pragma unroll
            for (int c = 0; c < 4; c++) acc[mi][ni][c] = 0.f;

    const __half* hT = g_hT + (size_t)bh * HDim * Ssz;

    for (int jt = 0; jt < 4; jt++) {
        __syncthreads();
        // stage Hs: 64 d-rows x 128 halfs
        {
            const int d = tid >> 2, p = tid & 3;
            const __half* src = hT + (size_t)d * Ssz + (jt << 7) + (p << 5);
            #pragma unroll
            for (int u = 0; u < 4; u++)
                *(uint4*)(Hs + d * 68 + (p << 4) + (u << 2)) =
                    *(const uint4*)(src + (u << 3));
        }
        __syncthreads();

        const int jb = jt << 7;
        #pragma unroll
        for (int ch = 0; ch < 8; ch++) {
            const int j0 = jb + (ch << 4) + (t << 1);
            const float4 d0 = dstP[j0],     d1 = dstP[j0 + 1];
            const float4 d8 = dstP[j0 + 8], d9 = dstP[j0 + 9];

            uint32_t bf[4][2];
            #pragma unroll
            for (int ni = 0; ni < 4; ni++) {
                const uint32_t* p = Hs + (wn + (ni << 3) + g) * 68 + (ch << 3) + t;
                bf[ni][0] = p[0];
                bf[ni][1] = p[4];
            }
            #pragma unroll
            for (int mi = 0; mi < 2; mi++) {
                const int qA = mi << 1, qB = qA + 1;
                const float pA0 = (d0.x >= thr[qA]) ? a1c[qA]*d0.y : a2c[qA]*d0.z;
                const float pA1 = (d1.x >= thr[qA]) ? a1c[qA]*d1.y : a2c[qA]*d1.z;
                const float pB0 = (d0.x >= thr[qB]) ? a1c[qB]*d0.y : a2c[qB]*d0.z;
                const float pB1 = (d1.x >= thr[qB]) ? a1c[qB]*d1.y : a2c[qB]*d1.z;
                const float pA8 = (d8.x >= thr[qA]) ? a1c[qA]*d8.y : a2c[qA]*d8.z;
                const float pA9 = (d9.x >= thr[qA]) ? a1c[qA]*d9.y : a2c[qA]*d9.z;
                const float pB8 = (d8.x >= thr[qB]) ? a1c[qB]*d8.y : a2c[qB]*d8.z;
                const float pB9 = (d9.x >= thr[qB]) ? a1c[qB]*d9.y : a2c[qB]*d9.z;
                uint32_t af[4];
                af[0] = pack2h(pA0, pA1);
                af[1] = pack2h(pB0, pB1);
                af[2] = pack2h(pA8, pA9);
                af[3] = pack2h(pB8, pB9);
                #pragma unroll
                for (int ni = 0; ni < 4; ni++)
                    mma16(acc[mi][ni], af, bf[ni]);
            }
        }
    }

    // ---- epilogue: acc -> g_att (bh, s, d) fp32 ----
    #pragma unroll
    for (int mi = 0; mi < 2; mi++) {
        #pragma unroll
        for (int half = 0; half < 2; half++) {
            const int row = i0 + wm + (mi << 4) + g + (half << 3);
            float* op = g_att + ((size_t)bh * Ssz + row) * HDim;
            #pragma unroll
            for (int ni = 0; ni < 4; ni++) {
                const int col = wn + (ni << 3) + (t << 1);
                *(float2*)(op + col) =
                    make_float2(acc[mi][ni][half*2], acc[mi][ni][half*2+1]);
            }
        }
    }
}

// ---------------------------------------------------------------------------
// LayerNorms
// ---------------------------------------------------------------------------
__device__ __forceinline__ void block_meanvar(float v0, float v1, int tid,
                                              float& mean, float& rstd)
{
    float s1 = v0 + v1;
    float s2 = v0 * v0 + v1 * v1;
    #pragma unroll
    for (int off = 16; off; off >>= 1) {
        s1 += __shfl_xor_sync(0xffffffffu, s1, off);
        s2 += __shfl_xor_sync(0xffffffffu, s2, off);
    }
    __shared__ float rs[8], rq[8];
    __shared__ float mn_s, rstd_s;
    const int lane = tid & 31, w = tid >> 5;
    if (lane == 0) { rs[w] = s1; rq[w] = s2; }
    __syncthreads();
    if (tid == 0) {
        float a = 0.f, c = 0.f;
        #pragma unroll
        for (int i = 0; i < 8; i++) { a += rs[i]; c += rq[i]; }
        const float m = a * (1.0f / 512.0f);
        const float var = c * (1.0f / 512.0f) - m * m;
        mn_s = m;
        rstd_s = rsqrtf(var + 1e-5f);
    }
    __syncthreads();
    mean = mn_s; rstd = rstd_s;
}

__global__ __launch_bounds__(256) void ln1_kernel(
    const float* __restrict__ x,
    const float* __restrict__ gw, const float* __restrict__ bw)
{
    const int m = blockIdx.x, tid = threadIdx.x;
    const int bb = m >> 9, s = m & 511;
    float v0, v1;
    {
        int d = tid;
        v0 = g_att[((((bb << 3) + (d >> 6)) << 9) + s) * HDim + (d & 63)]
           + x[(size_t)m * Dsz + d];
        d = tid + 256;
        v1 = g_att[((((bb << 3) + (d >> 6)) << 9) + s) * HDim + (d & 63)]
           + x[(size_t)m * Dsz + d];
    }
    float mean, rstd;
    block_meanvar(v0, v1, tid, mean, rstd);
    const float o0 = (v0 - mean) * rstd * gw[tid]       + bw[tid];
    const float o1 = (v1 - mean) * rstd * gw[tid + 256] + bw[tid + 256];
    g_y  [(size_t)m * Dsz + tid]       = o0;
    g_y  [(size_t)m * Dsz + tid + 256] = o1;
    g_y16[(size_t)m * Dsz + tid]       = __float2half(o0);
    g_y16[(size_t)m * Dsz + tid + 256] = __float2half(o1);
}

__global__ __launch_bounds__(256) void ln2_kernel(
    const float* __restrict__ gw, const float* __restrict__ bw,
    float* __restrict__ out)
{
    const int m = blockIdx.x, tid = threadIdx.x;
    const float v0 = g_pre2[(size_t)m * Dsz + tid];
    const float v1 = g_pre2[(size_t)m * Dsz + tid + 256];
    float mean, rstd;
    block_meanvar(v0, v1, tid, mean, rstd);
    out[(size_t)m * Dsz + tid]       = (v0 - mean) * rstd * gw[tid]       + bw[tid];
    out[(size_t)m * Dsz + tid + 256] = (v1 - mean) * rstd * gw[tid + 256] + bw[tid + 256];
}

// ---------------------------------------------------------------------------
// Launch. adj/sem_W/sem_b are provably dead (softmax output can never be
// exactly 0, so the mask is the identity) and are not read.
// ---------------------------------------------------------------------------
extern "C" void kernel_launch(void* const* d_in, const int* in_sizes, int n_in,
                              void* d_out, int out_size)
{
    const float* x     = (const float*)d_in[0];
    const float* w_W   = (const float*)d_in[2];
    const float* w_b   = (const float*)d_in[3];
    const float* a_w   = (const float*)d_in[4];
    const float* ff1_W = (const float*)d_in[7];
    const float* ff1_b = (const float*)d_in[8];
    const float* ff2_W = (const float*)d_in[9];
    const float* ff2_b = (const float*)d_in[10];
    const float* ln1_g = (const float*)d_in[11];
    const float* ln1_b = (const float*)d_in[12];
    const float* ln2_g = (const float*)d_in[13];
    const float* ln2_b = (const float*)d_in[14];
    float* out = (float*)d_out;

    __half* dx16;  cudaGetSymbolAddress((void**)&dx16,  g_x16);
    __half* dw16;  cudaGetSymbolAddress((void**)&dw16,  g_w16);
    __half* d1w16; cudaGetSymbolAddress((void**)&d1w16, g_f1w16);
    __half* d2w16; cudaGetSymbolAddress((void**)&d2w16, g_f2w16);
    __half* dy16;  cudaGetSymbolAddress((void**)&dy16,  g_y16);
    __half* dff16; cudaGetSymbolAddress((void**)&dff16, g_ff16);

    cudaFuncSetAttribute(mm_mma<1>, cudaFuncAttributeMaxDynamicSharedMemorySize, MM_SMEM);
    cudaFuncSetAttribute(mm_mma<2>, cudaFuncAttributeMaxDynamicSharedMemorySize, MM_SMEM);
    cudaFuncSetAttribute(mm_mma<3>, cudaFuncAttributeMaxDynamicSharedMemorySize, MM_SMEM);

    // 0) fp32 -> fp16 conversions
    f2h_kernel<<<(Mrows*Dsz)/1024, 256>>>(x, dx16, Mrows*Dsz);
    f2h_kernel<<<(Dsz*Dsz)/1024, 256>>>(w_W, dw16, Dsz*Dsz);
    f2h_kernel<<<(2*Dsz*Dsz)/1024, 256>>>(ff1_W, d1w16, 2*Dsz*Dsz);
    f2h_kernel<<<(2*Dsz*Dsz)/1024, 256>>>(ff2_W, d2w16, 2*Dsz*Dsz);

    // 1) h = x @ w_W^T + w_b -> g_h16 (bh,s,hd)
    mm_mma<1><<<dim3(Dsz/128, Mrows/128), 256, MM_SMEM>>>(dx16, dw16, w_b, Dsz, Dsz);
    // 2) transpose h -> g_hT (bh,d,s)
    h2t_kernel<<<dim3(Ssz/64, Bsz*Hh), 256>>>();
    // 3) src/dst projections
    src_dst_kernel<<<(Bsz*Hh*Ssz)/4, 128>>>(a_w);
    // 4) fused GAT attention -> g_att
    attn_mma_kernel<<<dim3(Ssz/128, Bsz*Hh), 256>>>();
    // 5) LN1(att + x) -> g_y (fp32) + g_y16
    ln1_kernel<<<Mrows, 256>>>(x, ln1_g, ln1_b);
    // 6) g_ff16 = GeLU(y @ ff1_W^T + ff1_b)
    mm_mma<2><<<dim3(2*Dsz/128, Mrows/128), 256, MM_SMEM>>>(dy16, d1w16, ff1_b, 2*Dsz, Dsz);
    // 7) g_pre2 = ff @ ff2_W^T + ff2_b + y
    mm_mma<3><<<dim3(Dsz/128, Mrows/128), 256, MM_SMEM>>>(dff16, d2w16, ff2_b, Dsz, 2*Dsz);
    // 8) LN2 -> out
    ln2_kernel<<<Mrows, 256>>>(ln2_g, ln2_b, out);
}

// round 11
// speedup vs baseline: 4.5239x; 1.2374x over previous
#include <cuda_runtime.h>
#include <cuda_fp16.h>
#include <math.h>
#include <stdint.h>

// Problem constants
#define Bsz 32
#define Ssz 512
#define Dsz 512
#define Hh  8
#define HDim 64
#define Mrows (Bsz*Ssz)          // 16384
#define NEG_SLOPE 0.2f

// ---------------------------------------------------------------------------
// Scratch (static __device__ arrays; allocation is forbidden)
// ---------------------------------------------------------------------------
__device__ __half g_x16 [Mrows*Dsz];         // x in fp16
__device__ __half g_w16 [Dsz*Dsz];           // w_W fp16
__device__ __half g_f1w16[2*Dsz*Dsz];        // ff1_W fp16
__device__ __half g_f2w16[2*Dsz*Dsz];        // ff2_W fp16
__device__ __half g_h16 [Bsz*Hh*Ssz*HDim];   // (bh,s,hd) projected heads fp16
__device__ __half g_hT  [Bsz*Hh*HDim*Ssz];   // (bh, d, s) fp16 transposed
__device__ float  g_src [Bsz*Hh*Ssz];
__device__ float  g_dst [Bsz*Hh*Ssz];
__device__ float  g_att [Bsz*Hh*Ssz*HDim];   // attention output fp32
__device__ float  g_y   [Mrows*Dsz];         // post-LN1 fp32 (residual for EPI3)
__device__ __half g_y16 [Mrows*Dsz];         // post-LN1 fp16 (mm2 input)
__device__ __half g_ff16[Mrows*2*Dsz];       // GeLU(ff1) fp16 (mm3 input)
__device__ float  g_pre2[Mrows*Dsz];         // ff2 out + residual (pre-LN2)

// ---------------------------------------------------------------------------
// helpers
// ---------------------------------------------------------------------------
__device__ __forceinline__ uint32_t pack2h(float x, float y) {
    __half2 h = __floats2half2_rn(x, y);
    return *reinterpret_cast<uint32_t*>(&h);
}
__device__ __forceinline__ uint32_t sm32(const void* p) {
    return (uint32_t)__cvta_generic_to_shared(p);
}
__device__ __forceinline__ void mma16(float* c, const uint32_t* a, const uint32_t* b) {
    asm volatile(
        "mma.sync.aligned.m16n8k16.row.col.f32.f16.f16.f32 "
        "{%0,%1,%2,%3}, {%4,%5,%6,%7}, {%8,%9}, {%0,%1,%2,%3};"
        : "+f"(c[0]), "+f"(c[1]), "+f"(c[2]), "+f"(c[3])
        : "r"(a[0]), "r"(a[1]), "r"(a[2]), "r"(a[3]), "r"(b[0]), "r"(b[1]));
}
__device__ __forceinline__ void ldm_x4(uint32_t* r, uint32_t saddr) {
    asm volatile(
        "ldmatrix.sync.aligned.m8n8.x4.shared.b16 {%0,%1,%2,%3}, [%4];"
        : "=r"(r[0]), "=r"(r[1]), "=r"(r[2]), "=r"(r[3]) : "r"(saddr));
}
#define CP16(sa, ga) asm volatile("cp.async.cg.shared.global [%0], [%1], 16;" :: "r"(sa), "l"(ga))
#define CPCOMMIT()   asm volatile("cp.async.commit_group;" ::: "memory")
#define CPWAIT1()    asm volatile("cp.async.wait_group 1;" ::: "memory")
#define CPWAIT0()    asm volatile("cp.async.wait_group 0;" ::: "memory")

// ---------------------------------------------------------------------------
// fp32 -> fp16 conversion, n % 1024 == 0
// ---------------------------------------------------------------------------
__global__ __launch_bounds__(256) void f2h_kernel(
    const float* __restrict__ s, __half* __restrict__ d, int n)
{
    const int i = (blockIdx.x * 256 + threadIdx.x) * 4;
    if (i < n) {
        float4 v = *(const float4*)(s + i);
        *(uint2*)(d + i) = make_uint2(pack2h(v.x, v.y), pack2h(v.z, v.w));
    }
}

// ---------------------------------------------------------------------------
// fp16 tensor-core GEMM: C = A @ W^T + bias. CTA 128x128, BK=32, 256 threads
// (8 warps, warp tile 64x32), m16n8k16, 3-stage cp.async, ldmatrix frag loads.
// EPI: 1 = + w_b -> g_h16 scatter AND fused transpose -> g_hT
//      2 = GeLU  -> g_ff16 fp16
//      3 = + residual g_y -> g_pre2 fp32
// ---------------------------------------------------------------------------
#define LDKu 20
#define MSTG (128*LDKu)            // 2560 u32 per stage per matrix
#define MM_SMEM (3*MSTG*4*2)       // 61440 B

template<int EPI>
__global__ __launch_bounds__(256, 2) void mm_mma(
    const __half* __restrict__ A, const __half* __restrict__ W,
    const float* __restrict__ bias, int N, int K)
{
    extern __shared__ uint32_t smm[];
    uint32_t* As = smm;                 // [3][MSTG]
    uint32_t* Bs = smm + 3*MSTG;        // [3][MSTG]
    const uint32_t smmB = sm32(smm);

    const int tid  = threadIdx.x;
    const int wid  = tid >> 5;
    const int lane = tid & 31;
    const int g    = lane >> 2;
    const int t    = lane & 3;
    const int bm   = blockIdx.y << 7;
    const int bn   = blockIdx.x << 7;
    const int wm   = (wid & 1) << 6;   // 0/64
    const int wn   = (wid >> 1) << 5;  // 0/32/64/96

    // ldmatrix per-lane source offsets (u32 units, within a stage)
    int aOff[4], bOff[4];
    {
        const int la = lane & 15, ha = lane >> 4;       // A: rows 0-15, half sel
        const int lb = lane & 7,  hb = (lane >> 3) & 3; // B: rows 0-7, quarter sel
        #pragma unroll
        for (int mi = 0; mi < 4; mi++)
            aOff[mi] = (wm + (mi << 4) + la) * LDKu + (ha << 2);
        #pragma unroll
        for (int ni = 0; ni < 4; ni++)
            bOff[ni] = (wn + (ni << 3) + lb) * LDKu + (hb << 2);
    }

    float acc[4][4][4];
    #pragma unroll
    for (int mi = 0; mi < 4; mi++)
        #pragma unroll
        for (int ni = 0; ni < 4; ni++)
            #pragma unroll
            for (int c = 0; c < 4; c++) acc[mi][ni][c] = 0.f;

    auto issue = [&](int kt, int slot) {
        const int k0 = kt << 5;
        #pragma unroll
        for (int u = 0; u < 2; u++) {
            const int idx = tid + (u << 8);
            const int r = idx >> 2, c = idx & 3;
            const __half* ga = A + (size_t)(bm + r) * K + k0 + (c << 3);
            const __half* gb = W + (size_t)(bn + r) * K + k0 + (c << 3);
            CP16(sm32(As + slot*MSTG + r*LDKu + (c << 2)), ga);
            CP16(sm32(Bs + slot*MSTG + r*LDKu + (c << 2)), gb);
        }
        CPCOMMIT();
    };

    const int nkt = K >> 5;
    issue(0, 0);
    issue(1, 1);

    for (int kt = 0; kt < nkt; kt++) {
        if (kt + 1 < nkt) { CPWAIT1(); } else { CPWAIT0(); }
        __syncthreads();
        if (kt + 2 < nkt) issue(kt + 2, (kt + 2) % 3);

        const uint32_t AbB = smmB + (((kt % 3) * MSTG) << 2);
        const uint32_t BbB = smmB + ((((kt % 3) + 3) * MSTG) << 2);

        uint32_t bfr[4][4];
        #pragma unroll
        for (int ni = 0; ni < 4; ni++)
            ldm_x4(bfr[ni], BbB + (bOff[ni] << 2));

        #pragma unroll
        for (int kc = 0; kc < 2; kc++) {
            uint32_t afr[4][4];
            #pragma unroll
            for (int mi = 0; mi < 4; mi++)
                ldm_x4(afr[mi], AbB + ((aOff[mi] + (kc << 3)) << 2));
            #pragma unroll
            for (int mi = 0; mi < 4; mi++)
                #pragma unroll
                for (int ni = 0; ni < 4; ni++)
                    mma16(acc[mi][ni], afr[mi], &bfr[ni][kc << 1]);
        }
    }

    // ---------------- epilogue ----------------
    if (EPI == 1) {
        // write g_h16 (bh,s,hd) AND transposed g_hT (bh,d,s) via smem reuse
        __syncthreads();
        __half* trsp = (__half*)smm;   // [128 cols][136 rows-pad]
        #pragma unroll
        for (int ni = 0; ni < 4; ni++) {
            const int lcol = wn + (ni << 3) + (t << 1);
            const float2 bb = *(const float2*)&bias[bn + lcol];
            #pragma unroll
            for (int mi = 0; mi < 4; mi++) {
                #pragma unroll
                for (int half = 0; half < 2; half++) {
                    const int lrow = wm + (mi << 4) + g + (half << 3);
                    const float vx = acc[mi][ni][half*2+0] + bb.x;
                    const float vy = acc[mi][ni][half*2+1] + bb.y;
                    const int row = bm + lrow;
                    const int bI = row >> 9, sI = row & 511;
                    const int col = bn + lcol;
                    const int hh = col >> 6, hd = col & 63;
                    *(uint32_t*)&g_h16[((size_t)(((bI << 3) + hh) << 9) + sI) * HDim + hd] =
                        pack2h(vx, vy);
                    trsp[lcol * 136 + lrow]       = __float2half(vx);
                    trsp[(lcol + 1) * 136 + lrow] = __float2half(vy);
                }
            }
        }
        __syncthreads();
        const int bI = bm >> 9, s0 = bm & 511;
        #pragma unroll
        for (int u = 0; u < 8; u++) {
            const int idx = tid + (u << 8);      // 0..2047
            const int lc = idx >> 4;             // local col 0..127
            const int sc = (idx & 15) << 3;      // s offset 0..120
            uint4 val = *(uint4*)&trsp[lc * 136 + sc];
            const int col = bn + lc;
            const int hh = col >> 6, d = col & 63;
            *(uint4*)&g_hT[((size_t)((bI << 3) + hh) * HDim + d) * Ssz + s0 + sc] = val;
        }
    } else {
        #pragma unroll
        for (int ni = 0; ni < 4; ni++) {
            const int col = bn + wn + (ni << 3) + (t << 1);
            const float2 bb = *(const float2*)&bias[col];
            #pragma unroll
            for (int mi = 0; mi < 4; mi++) {
                #pragma unroll
                for (int half = 0; half < 2; half++) {
                    const int row = bm + wm + (mi << 4) + g + (half << 3);
                    float2 v;
                    v.x = acc[mi][ni][half*2+0] + bb.x;
                    v.y = acc[mi][ni][half*2+1] + bb.y;
                    if (EPI == 2) {
                        v.x = 0.5f*v.x*(1.f + erff(v.x*0.70710678118654752f));
                        v.y = 0.5f*v.y*(1.f + erff(v.y*0.70710678118654752f));
                        *(uint32_t*)&g_ff16[(size_t)row * N + col] = pack2h(v.x, v.y);
                    } else {
                        const float2 rr = *(const float2*)&g_y[(size_t)row * Dsz + col];
                        v.x += rr.x; v.y += rr.y;
                        *(float2*)&g_pre2[(size_t)row * Dsz + col] = v;
                    }
                }
            }
        }
    }
}

// ---------------------------------------------------------------------------
// src/dst projections: one warp per (b,h,s) row of g_h16
// ---------------------------------------------------------------------------
__global__ __launch_bounds__(128) void src_dst_kernel(const float* __restrict__ a_w)
{
    const int row  = blockIdx.x * 4 + (threadIdx.x >> 5);
    const int lane = threadIdx.x & 31;
    const __half* hrow = g_h16 + (size_t)row * HDim;
    const float v0 = __half2float(hrow[lane]);
    const float v1 = __half2float(hrow[lane + 32]);
    float s = v0 * a_w[lane]      + v1 * a_w[lane + 32];
    float d = v0 * a_w[64 + lane] + v1 * a_w[96 + lane];
    #pragma unroll
    for (int off = 16; off; off >>= 1) {
        s += __shfl_xor_sync(0xffffffffu, s, off);
        d += __shfl_xor_sync(0xffffffffu, d, off);
    }
    if (lane == 0) { g_src[row] = s; g_dst[row] = d; }
}

// ---------------------------------------------------------------------------
// Fused GAT attention, tensor-core AV, P generated directly in mma A-fragment
// registers. P[i][j] = (d_j >= -s_i) ? e^{s_i}E1[j]/Z_i : e^{.2 s_i}E2[j]/Z_i
// ---------------------------------------------------------------------------
__global__ __launch_bounds__(256, 1) void attn_mma_kernel()
{
    __shared__ float4  dstP[512];          // {raw, e^d, e^{0.2d}, 0}
    __shared__ float   srcS[128];
    __shared__ float   red [256];
    __shared__ uint32_t Hs [64*68];

    const int bh  = blockIdx.y;
    const int i0  = blockIdx.x << 7;
    const int tid = threadIdx.x;
    const int wid = tid >> 5, lane = tid & 31;
    const int g = lane >> 2, t = lane & 3;
    const int wm = (wid & 3) << 5;
    const int wn = (wid >> 2) << 5;

    const float* dstp = g_dst + bh * Ssz;
    for (int u = tid; u < 512; u += 256) {
        const float dv = dstp[u];
        dstP[u] = make_float4(dv, __expf(dv), __expf(NEG_SLOPE * dv), 0.f);
    }
    if (tid < 128) srcS[tid] = g_src[bh * Ssz + i0 + tid];
    __syncthreads();

    {
        const int r = tid >> 1, q2 = tid & 1;
        const float sv = srcS[r];
        const float e1 = __expf(sv), e2 = __expf(NEG_SLOPE * sv);
        float ps = 0.f;
        #pragma unroll 4
        for (int jj = 0; jj < 256; jj++) {
            const float4 dp = dstP[(q2 << 8) + jj];
            ps += ((sv + dp.x) >= 0.f) ? e1 * dp.y : e2 * dp.z;
        }
        red[tid] = ps;
    }
    __syncthreads();

    float thr[4], a1c[4], a2c[4];
    #pragma unroll
    for (int q = 0; q < 4; q++) {
        const int rr = wm + (q << 3) + g;
        const float sv = srcS[rr];
        const float invD = 1.0f / (red[2*rr] + red[2*rr + 1]);
        thr[q] = -sv;
        a1c[q] = __expf(sv) * invD;
        a2c[q] = __expf(NEG_SLOPE * sv) * invD;
    }

    float acc[2][4][4];
    #pragma unroll
    for (int mi = 0; mi < 2; mi++)
        #pragma unroll
        for (int ni = 0; ni < 4; ni++)
            #pragma unroll
            for (int c = 0; c < 4; c++) acc[mi][ni][c] = 0.f;

    const __half* hT = g_hT + (size_t)bh * HDim * Ssz;

    for (int jt = 0; jt < 4; jt++) {
        __syncthreads();
        {
            const int d = tid >> 2, p = tid & 3;
            const __half* src = hT + (size_t)d * Ssz + (jt << 7) + (p << 5);
            #pragma unroll
            for (int u = 0; u < 4; u++)
                *(uint4*)(Hs + d * 68 + (p << 4) + (u << 2)) =
                    *(const uint4*)(src + (u << 3));
        }
        __syncthreads();

        const int jb = jt << 7;
        #pragma unroll
        for (int ch = 0; ch < 8; ch++) {
            const int j0 = jb + (ch << 4) + (t << 1);
            const float4 d0 = dstP[j0],     d1 = dstP[j0 + 1];
            const float4 d8 = dstP[j0 + 8], d9 = dstP[j0 + 9];

            uint32_t bf[4][2];
            #pragma unroll
            for (int ni = 0; ni < 4; ni++) {
                const uint32_t* p = Hs + (wn + (ni << 3) + g) * 68 + (ch << 3) + t;
                bf[ni][0] = p[0];
                bf[ni][1] = p[4];
            }
            #pragma unroll
            for (int mi = 0; mi < 2; mi++) {
                const int qA = mi << 1, qB = qA + 1;
                const float pA0 = (d0.x >= thr[qA]) ? a1c[qA]*d0.y : a2c[qA]*d0.z;
                const float pA1 = (d1.x >= thr[qA]) ? a1c[qA]*d1.y : a2c[qA]*d1.z;
                const float pB0 = (d0.x >= thr[qB]) ? a1c[qB]*d0.y : a2c[qB]*d0.z;
                const float pB1 = (d1.x >= thr[qB]) ? a1c[qB]*d1.y : a2c[qB]*d1.z;
                const float pA8 = (d8.x >= thr[qA]) ? a1c[qA]*d8.y : a2c[qA]*d8.z;
                const float pA9 = (d9.x >= thr[qA]) ? a1c[qA]*d9.y : a2c[qA]*d9.z;
                const float pB8 = (d8.x >= thr[qB]) ? a1c[qB]*d8.y : a2c[qB]*d8.z;
                const float pB9 = (d9.x >= thr[qB]) ? a1c[qB]*d9.y : a2c[qB]*d9.z;
                uint32_t af[4];
                af[0] = pack2h(pA0, pA1);
                af[1] = pack2h(pB0, pB1);
                af[2] = pack2h(pA8, pA9);
                af[3] = pack2h(pB8, pB9);
                #pragma unroll
                for (int ni = 0; ni < 4; ni++)
                    mma16(acc[mi][ni], af, bf[ni]);
            }
        }
    }

    #pragma unroll
    for (int mi = 0; mi < 2; mi++) {
        #pragma unroll
        for (int half = 0; half < 2; half++) {
            const int row = i0 + wm + (mi << 4) + g + (half << 3);
            float* op = g_att + ((size_t)bh * Ssz + row) * HDim;
            #pragma unroll
            for (int ni = 0; ni < 4; ni++) {
                const int col = wn + (ni << 3) + (t << 1);
                *(float2*)(op + col) =
                    make_float2(acc[mi][ni][half*2], acc[mi][ni][half*2+1]);
            }
        }
    }
}

// ---------------------------------------------------------------------------
// LayerNorms
// ---------------------------------------------------------------------------
__device__ __forceinline__ void block_meanvar(float v0, float v1, int tid,
                                              float& mean, float& rstd)
{
    float s1 = v0 + v1;
    float s2 = v0 * v0 + v1 * v1;
    #pragma unroll
    for (int off = 16; off; off >>= 1) {
        s1 += __shfl_xor_sync(0xffffffffu, s1, off);
        s2 += __shfl_xor_sync(0xffffffffu, s2, off);
    }
    __shared__ float rs[8], rq[8];
    __shared__ float mn_s, rstd_s;
    const int lane = tid & 31, w = tid >> 5;
    if (lane == 0) { rs[w] = s1; rq[w] = s2; }
    __syncthreads();
    if (tid == 0) {
        float a = 0.f, c = 0.f;
        #pragma unroll
        for (int i = 0; i < 8; i++) { a += rs[i]; c += rq[i]; }
        const float m = a * (1.0f / 512.0f);
        const float var = c * (1.0f / 512.0f) - m * m;
        mn_s = m;
        rstd_s = rsqrtf(var + 1e-5f);
    }
    __syncthreads();
    mean = mn_s; rstd = rstd_s;
}

__global__ __launch_bounds__(256) void ln1_kernel(
    const float* __restrict__ x,
    const float* __restrict__ gw, const float* __restrict__ bw)
{
    const int m = blockIdx.x, tid = threadIdx.x;
    const int bb = m >> 9, s = m & 511;
    float v0, v1;
    {
        int d = tid;
        v0 = g_att[((((bb << 3) + (d >> 6)) << 9) + s) * HDim + (d & 63)]
           + x[(size_t)m * Dsz + d];
        d = tid + 256;
        v1 = g_att[((((bb << 3) + (d >> 6)) << 9) + s) * HDim + (d & 63)]
           + x[(size_t)m * Dsz + d];
    }
    float mean, rstd;
    block_meanvar(v0, v1, tid, mean, rstd);
    const float o0 = (v0 - mean) * rstd * gw[tid]       + bw[tid];
    const float o1 = (v1 - mean) * rstd * gw[tid + 256] + bw[tid + 256];
    g_y  [(size_t)m * Dsz + tid]       = o0;
    g_y  [(size_t)m * Dsz + tid + 256] = o1;
    g_y16[(size_t)m * Dsz + tid]       = __float2half(o0);
    g_y16[(size_t)m * Dsz + tid + 256] = __float2half(o1);
}

__global__ __launch_bounds__(256) void ln2_kernel(
    const float* __restrict__ gw, const float* __restrict__ bw,
    float* __restrict__ out)
{
    const int m = blockIdx.x, tid = threadIdx.x;
    const float v0 = g_pre2[(size_t)m * Dsz + tid];
    const float v1 = g_pre2[(size_t)m * Dsz + tid + 256];
    float mean, rstd;
    block_meanvar(v0, v1, tid, mean, rstd);
    out[(size_t)m * Dsz + tid]       = (v0 - mean) * rstd * gw[tid]       + bw[tid];
    out[(size_t)m * Dsz + tid + 256] = (v1 - mean) * rstd * gw[tid + 256] + bw[tid + 256];
}

// ---------------------------------------------------------------------------
// Launch. adj/sem_W/sem_b are provably dead (softmax output can never be
// exactly 0, so the mask is the identity) and are not read.
// ---------------------------------------------------------------------------
extern "C" void kernel_launch(void* const* d_in, const int* in_sizes, int n_in,
                              void* d_out, int out_size)
{
    const float* x     = (const float*)d_in[0];
    const float* w_W   = (const float*)d_in[2];
    const float* w_b   = (const float*)d_in[3];
    const float* a_w   = (const float*)d_in[4];
    const float* ff1_W = (const float*)d_in[7];
    const float* ff1_b = (const float*)d_in[8];
    const float* ff2_W = (const float*)d_in[9];
    const float* ff2_b = (const float*)d_in[10];
    const float* ln1_g = (const float*)d_in[11];
    const float* ln1_b = (const float*)d_in[12];
    const float* ln2_g = (const float*)d_in[13];
    const float* ln2_b = (const float*)d_in[14];
    float* out = (float*)d_out;

    __half* dx16;  cudaGetSymbolAddress((void**)&dx16,  g_x16);
    __half* dw16;  cudaGetSymbolAddress((void**)&dw16,  g_w16);
    __half* d1w16; cudaGetSymbolAddress((void**)&d1w16, g_f1w16);
    __half* d2w16; cudaGetSymbolAddress((void**)&d2w16, g_f2w16);
    __half* dy16;  cudaGetSymbolAddress((void**)&dy16,  g_y16);
    __half* dff16; cudaGetSymbolAddress((void**)&dff16, g_ff16);

    cudaFuncSetAttribute(mm_mma<1>, cudaFuncAttributeMaxDynamicSharedMemorySize, MM_SMEM);
    cudaFuncSetAttribute(mm_mma<2>, cudaFuncAttributeMaxDynamicSharedMemorySize, MM_SMEM);
    cudaFuncSetAttribute(mm_mma<3>, cudaFuncAttributeMaxDynamicSharedMemorySize, MM_SMEM);

    // 0) fp32 -> fp16 conversions
    f2h_kernel<<<(Mrows*Dsz)/1024, 256>>>(x, dx16, Mrows*Dsz);
    f2h_kernel<<<(Dsz*Dsz)/1024, 256>>>(w_W, dw16, Dsz*Dsz);
    f2h_kernel<<<(2*Dsz*Dsz)/1024, 256>>>(ff1_W, d1w16, 2*Dsz*Dsz);
    f2h_kernel<<<(2*Dsz*Dsz)/1024, 256>>>(ff2_W, d2w16, 2*Dsz*Dsz);

    // 1) h = x @ w_W^T + w_b -> g_h16 (bh,s,hd) + fused transpose -> g_hT
    mm_mma<1><<<dim3(Dsz/128, Mrows/128), 256, MM_SMEM>>>(dx16, dw16, w_b, Dsz, Dsz);
    // 2) src/dst projections
    src_dst_kernel<<<(Bsz*Hh*Ssz)/4, 128>>>(a_w);
    // 3) fused GAT attention -> g_att
    attn_mma_kernel<<<dim3(Ssz/128, Bsz*Hh), 256>>>();
    // 4) LN1(att + x) -> g_y (fp32) + g_y16
    ln1_kernel<<<Mrows, 256>>>(x, ln1_g, ln1_b);
    // 5) g_ff16 = GeLU(y @ ff1_W^T + ff1_b)
    mm_mma<2><<<dim3(2*Dsz/128, Mrows/128), 256, MM_SMEM>>>(dy16, d1w16, ff1_b, 2*Dsz, Dsz);
    // 6) g_pre2 = ff @ ff2_W^T + ff2_b + y
    mm_mma<3><<<dim3(Dsz/128, Mrows/128), 256, MM_SMEM>>>(dff16, d2w16, ff2_b, Dsz, 2*Dsz);
    // 7) LN2 -> out
    ln2_kernel<<<Mrows, 256>>>(ln2_g, ln2_b, out);
}

// round 12
// speedup vs baseline: 5.0422x; 1.1146x over previous
#include <cuda_runtime.h>
#include <cuda_fp16.h>
#include <math.h>
#include <stdint.h>

// Problem constants
#define Bsz 32
#define Ssz 512
#define Dsz 512
#define Hh  8
#define HDim 64
#define Mrows (Bsz*Ssz)          // 16384
#define NEG_SLOPE 0.2f

// ---------------------------------------------------------------------------
// Scratch (static __device__ arrays; allocation is forbidden)
// ---------------------------------------------------------------------------
__device__ __half g_x16 [Mrows*Dsz];         // x in fp16
__device__ __half g_w16 [Dsz*Dsz];           // w_W fp16
__device__ __half g_f1w16[2*Dsz*Dsz];        // ff1_W fp16
__device__ __half g_f2w16[2*Dsz*Dsz];        // ff2_W fp16
__device__ __half g_hT  [Bsz*Hh*HDim*Ssz];   // (bh, d, s) fp16 transposed heads
__device__ float  g_src [Bsz*Hh*Ssz];
__device__ float  g_dst [Bsz*Hh*Ssz];
__device__ float  g_att [Bsz*Hh*Ssz*HDim];   // attention output fp32
__device__ float  g_y   [Mrows*Dsz];         // post-LN1 fp32 (residual for EPI3)
__device__ __half g_y16 [Mrows*Dsz];         // post-LN1 fp16 (mm2 input)
__device__ __half g_ff16[Mrows*2*Dsz];       // GeLU(ff1) fp16 (mm3 input)
__device__ float  g_pre2[Mrows*Dsz];         // ff2 out + residual (pre-LN2)

// ---------------------------------------------------------------------------
// helpers
// ---------------------------------------------------------------------------
__device__ __forceinline__ uint32_t pack2h(float x, float y) {
    __half2 h = __floats2half2_rn(x, y);
    return *reinterpret_cast<uint32_t*>(&h);
}
__device__ __forceinline__ uint32_t sm32(const void* p) {
    return (uint32_t)__cvta_generic_to_shared(p);
}
__device__ __forceinline__ void mma16(float* c, const uint32_t* a, const uint32_t* b) {
    asm volatile(
        "mma.sync.aligned.m16n8k16.row.col.f32.f16.f16.f32 "
        "{%0,%1,%2,%3}, {%4,%5,%6,%7}, {%8,%9}, {%0,%1,%2,%3};"
        : "+f"(c[0]), "+f"(c[1]), "+f"(c[2]), "+f"(c[3])
        : "r"(a[0]), "r"(a[1]), "r"(a[2]), "r"(a[3]), "r"(b[0]), "r"(b[1]));
}
__device__ __forceinline__ void ldm_x4(uint32_t* r, uint32_t saddr) {
    asm volatile(
        "ldmatrix.sync.aligned.m8n8.x4.shared.b16 {%0,%1,%2,%3}, [%4];"
        : "=r"(r[0]), "=r"(r[1]), "=r"(r[2]), "=r"(r[3]) : "r"(saddr));
}
#define CP16(sa, ga) asm volatile("cp.async.cg.shared.global [%0], [%1], 16;" :: "r"(sa), "l"(ga))
#define CPCOMMIT()   asm volatile("cp.async.commit_group;" ::: "memory")
#define CPWAIT1()    asm volatile("cp.async.wait_group 1;" ::: "memory")
#define CPWAIT0()    asm volatile("cp.async.wait_group 0;" ::: "memory")

// ---------------------------------------------------------------------------
// fused fp32 -> fp16 conversion of 4 arrays (all sizes % 1024 == 0)
// ---------------------------------------------------------------------------
__global__ __launch_bounds__(256) void f2h4_kernel(
    const float* __restrict__ s0, __half* __restrict__ d0, int n0,
    const float* __restrict__ s1, __half* __restrict__ d1, int n1,
    const float* __restrict__ s2, __half* __restrict__ d2, int n2,
    const float* __restrict__ s3, __half* __restrict__ d3, int n3)
{
    int i = (blockIdx.x * 256 + threadIdx.x) * 4;
    const float* s; __half* d;
    if (i < n0)                { s = s0; d = d0; }
    else if ((i -= n0) < n1)   { s = s1; d = d1; }
    else if ((i -= n1) < n2)   { s = s2; d = d2; }
    else if ((i -= n2) < n3)   { s = s3; d = d3; }
    else return;
    float4 v = *(const float4*)(s + i);
    *(uint2*)(d + i) = make_uint2(pack2h(v.x, v.y), pack2h(v.z, v.w));
}

// ---------------------------------------------------------------------------
// fp16 tensor-core GEMM: C = A @ W^T + bias. CTA 128x128, BK=32, 256 threads
// (8 warps, warp tile 64x32), m16n8k16, 3-stage cp.async, ldmatrix frags.
// EPI: 1 = + w_b, fused transpose -> g_hT only
//      2 = GeLU  -> g_ff16 fp16
//      3 = + residual g_y -> g_pre2 fp32
// ---------------------------------------------------------------------------
#define LDKu 20
#define MSTG (128*LDKu)            // 2560 u32 per stage per matrix
#define MM_SMEM (3*MSTG*4*2)       // 61440 B

template<int EPI>
__global__ __launch_bounds__(256, 2) void mm_mma(
    const __half* __restrict__ A, const __half* __restrict__ W,
    const float* __restrict__ bias, int N, int K)
{
    extern __shared__ uint32_t smm[];
    uint32_t* As = smm;                 // [3][MSTG]
    uint32_t* Bs = smm + 3*MSTG;        // [3][MSTG]
    const uint32_t smmB = sm32(smm);

    const int tid  = threadIdx.x;
    const int wid  = tid >> 5;
    const int lane = tid & 31;
    const int g    = lane >> 2;
    const int t    = lane & 3;
    const int bm   = blockIdx.y << 7;
    const int bn   = blockIdx.x << 7;
    const int wm   = (wid & 1) << 6;   // 0/64
    const int wn   = (wid >> 1) << 5;  // 0/32/64/96

    int aOff[4], bOff[4];
    {
        const int la = lane & 15, ha = lane >> 4;
        const int lb = lane & 7,  hb = (lane >> 3) & 3;
        #pragma unroll
        for (int mi = 0; mi < 4; mi++)
            aOff[mi] = (wm + (mi << 4) + la) * LDKu + (ha << 2);
        #pragma unroll
        for (int ni = 0; ni < 4; ni++)
            bOff[ni] = (wn + (ni << 3) + lb) * LDKu + (hb << 2);
    }

    float acc[4][4][4];
    #pragma unroll
    for (int mi = 0; mi < 4; mi++)
        #pragma unroll
        for (int ni = 0; ni < 4; ni++)
            #pragma unroll
            for (int c = 0; c < 4; c++) acc[mi][ni][c] = 0.f;

    auto issue = [&](int kt, int slot) {
        const int k0 = kt << 5;
        #pragma unroll
        for (int u = 0; u < 2; u++) {
            const int idx = tid + (u << 8);
            const int r = idx >> 2, c = idx & 3;
            const __half* ga = A + (size_t)(bm + r) * K + k0 + (c << 3);
            const __half* gb = W + (size_t)(bn + r) * K + k0 + (c << 3);
            CP16(sm32(As + slot*MSTG + r*LDKu + (c << 2)), ga);
            CP16(sm32(Bs + slot*MSTG + r*LDKu + (c << 2)), gb);
        }
        CPCOMMIT();
    };

    const int nkt = K >> 5;
    issue(0, 0);
    issue(1, 1);

    for (int kt = 0; kt < nkt; kt++) {
        if (kt + 1 < nkt) { CPWAIT1(); } else { CPWAIT0(); }
        __syncthreads();
        if (kt + 2 < nkt) issue(kt + 2, (kt + 2) % 3);

        const uint32_t AbB = smmB + (((kt % 3) * MSTG) << 2);
        const uint32_t BbB = smmB + ((((kt % 3) + 3) * MSTG) << 2);

        uint32_t bfr[4][4];
        #pragma unroll
        for (int ni = 0; ni < 4; ni++)
            ldm_x4(bfr[ni], BbB + (bOff[ni] << 2));

        #pragma unroll
        for (int kc = 0; kc < 2; kc++) {
            uint32_t afr[4][4];
            #pragma unroll
            for (int mi = 0; mi < 4; mi++)
                ldm_x4(afr[mi], AbB + ((aOff[mi] + (kc << 3)) << 2));
            #pragma unroll
            for (int mi = 0; mi < 4; mi++)
                #pragma unroll
                for (int ni = 0; ni < 4; ni++)
                    mma16(acc[mi][ni], afr[mi], &bfr[ni][kc << 1]);
        }
    }

    // ---------------- epilogue ----------------
    if (EPI == 1) {
        // fused transpose -> g_hT (bh,d,s) only (g_h16 eliminated)
        __syncthreads();
        __half* trsp = (__half*)smm;   // [128 cols][136 rows-pad]
        #pragma unroll
        for (int ni = 0; ni < 4; ni++) {
            const int lcol = wn + (ni << 3) + (t << 1);
            const float2 bb = *(const float2*)&bias[bn + lcol];
            #pragma unroll
            for (int mi = 0; mi < 4; mi++) {
                #pragma unroll
                for (int half = 0; half < 2; half++) {
                    const int lrow = wm + (mi << 4) + g + (half << 3);
                    trsp[lcol * 136 + lrow]       = __float2half(acc[mi][ni][half*2+0] + bb.x);
                    trsp[(lcol + 1) * 136 + lrow] = __float2half(acc[mi][ni][half*2+1] + bb.y);
                }
            }
        }
        __syncthreads();
        const int bI = bm >> 9, s0 = bm & 511;
        #pragma unroll
        for (int u = 0; u < 8; u++) {
            const int idx = tid + (u << 8);      // 0..2047
            const int lc = idx >> 4;             // local col 0..127
            const int sc = (idx & 15) << 3;      // s offset 0..120
            uint4 val = *(uint4*)&trsp[lc * 136 + sc];
            const int col = bn + lc;
            const int hh = col >> 6, d = col & 63;
            *(uint4*)&g_hT[((size_t)((bI << 3) + hh) * HDim + d) * Ssz + s0 + sc] = val;
        }
    } else {
        #pragma unroll
        for (int ni = 0; ni < 4; ni++) {
            const int col = bn + wn + (ni << 3) + (t << 1);
            const float2 bb = *(const float2*)&bias[col];
            #pragma unroll
            for (int mi = 0; mi < 4; mi++) {
                #pragma unroll
                for (int half = 0; half < 2; half++) {
                    const int row = bm + wm + (mi << 4) + g + (half << 3);
                    float2 v;
                    v.x = acc[mi][ni][half*2+0] + bb.x;
                    v.y = acc[mi][ni][half*2+1] + bb.y;
                    if (EPI == 2) {
                        v.x = 0.5f*v.x*(1.f + erff(v.x*0.70710678118654752f));
                        v.y = 0.5f*v.y*(1.f + erff(v.y*0.70710678118654752f));
                        *(uint32_t*)&g_ff16[(size_t)row * N + col] = pack2h(v.x, v.y);
                    } else {
                        const float2 rr = *(const float2*)&g_y[(size_t)row * Dsz + col];
                        v.x += rr.x; v.y += rr.y;
                        *(float2*)&g_pre2[(size_t)row * Dsz + col] = v;
                    }
                }
            }
        }
    }
}

// ---------------------------------------------------------------------------
// src/dst projections from g_hT: block per (b,h); thread owns s = 2*tid, 2*tid+1
// ---------------------------------------------------------------------------
__global__ __launch_bounds__(256) void src_dst_kernel(const float* __restrict__ a_w)
{
    __shared__ float asrc[64], adst[64];
    const int bh  = blockIdx.x;
    const int tid = threadIdx.x;
    if (tid < 64)       asrc[tid]       = a_w[tid];
    else if (tid < 128) adst[tid - 64]  = a_w[tid];
    __syncthreads();

    const __half* hT = g_hT + (size_t)bh * HDim * Ssz;
    float sA = 0.f, dA = 0.f, sB = 0.f, dB = 0.f;
    #pragma unroll 8
    for (int d = 0; d < 64; d++) {
        const __half2 h = *(const __half2*)(hT + (size_t)d * Ssz + (tid << 1));
        const float2 f = __half22float2(h);
        sA += f.x * asrc[d]; dA += f.x * adst[d];
        sB += f.y * asrc[d]; dB += f.y * adst[d];
    }
    *(float2*)&g_src[bh * Ssz + (tid << 1)] = make_float2(sA, sB);
    *(float2*)&g_dst[bh * Ssz + (tid << 1)] = make_float2(dA, dB);
}

// ---------------------------------------------------------------------------
// Fused GAT attention, tensor-core AV, P generated directly in mma A-fragment
// registers. P[i][j] = (d_j >= -s_i) ? e^{s_i}E1[j]/Z_i : e^{.2 s_i}E2[j]/Z_i
// ---------------------------------------------------------------------------
__global__ __launch_bounds__(256, 2) void attn_mma_kernel()
{
    __shared__ float4  dstP[512];          // {raw, e^d, e^{0.2d}, 0}
    __shared__ float   srcS[128];
    __shared__ float   red [256];
    __shared__ uint32_t Hs [64*68];

    const int bh  = blockIdx.y;
    const int i0  = blockIdx.x << 7;
    const int tid = threadIdx.x;
    const int wid = tid >> 5, lane = tid & 31;
    const int g = lane >> 2, t = lane & 3;
    const int wm = (wid & 3) << 5;
    const int wn = (wid >> 2) << 5;

    const float* dstp = g_dst + bh * Ssz;
    for (int u = tid; u < 512; u += 256) {
        const float dv = dstp[u];
        dstP[u] = make_float4(dv, __expf(dv), __expf(NEG_SLOPE * dv), 0.f);
    }
    if (tid < 128) srcS[tid] = g_src[bh * Ssz + i0 + tid];
    __syncthreads();

    {
        const int r = tid >> 1, q2 = tid & 1;
        const float sv = srcS[r];
        const float e1 = __expf(sv), e2 = __expf(NEG_SLOPE * sv);
        float ps = 0.f;
        #pragma unroll 4
        for (int jj = 0; jj < 256; jj++) {
            const float4 dp = dstP[(q2 << 8) + jj];
            ps += ((sv + dp.x) >= 0.f) ? e1 * dp.y : e2 * dp.z;
        }
        red[tid] = ps;
    }
    __syncthreads();

    float thr[4], a1c[4], a2c[4];
    #pragma unroll
    for (int q = 0; q < 4; q++) {
        const int rr = wm + (q << 3) + g;
        const float sv = srcS[rr];
        const float invD = 1.0f / (red[2*rr] + red[2*rr + 1]);
        thr[q] = -sv;
        a1c[q] = __expf(sv) * invD;
        a2c[q] = __expf(NEG_SLOPE * sv) * invD;
    }

    float acc[2][4][4];
    #pragma unroll
    for (int mi = 0; mi < 2; mi++)
        #pragma unroll
        for (int ni = 0; ni < 4; ni++)
            #pragma unroll
            for (int c = 0; c < 4; c++) acc[mi][ni][c] = 0.f;

    const __half* hT = g_hT + (size_t)bh * HDim * Ssz;

    for (int jt = 0; jt < 4; jt++) {
        __syncthreads();
        {
            const int d = tid >> 2, p = tid & 3;
            const __half* src = hT + (size_t)d * Ssz + (jt << 7) + (p << 5);
            #pragma unroll
            for (int u = 0; u < 4; u++)
                *(uint4*)(Hs + d * 68 + (p << 4) + (u << 2)) =
                    *(const uint4*)(src + (u << 3));
        }
        __syncthreads();

        const int jb = jt << 7;
        #pragma unroll
        for (int ch = 0; ch < 8; ch++) {
            const int j0 = jb + (ch << 4) + (t << 1);
            const float4 d0 = dstP[j0],     d1 = dstP[j0 + 1];
            const float4 d8 = dstP[j0 + 8], d9 = dstP[j0 + 9];

            uint32_t bf[4][2];
            #pragma unroll
            for (int ni = 0; ni < 4; ni++) {
                const uint32_t* p = Hs + (wn + (ni << 3) + g) * 68 + (ch << 3) + t;
                bf[ni][0] = p[0];
                bf[ni][1] = p[4];
            }
            #pragma unroll
            for (int mi = 0; mi < 2; mi++) {
                const int qA = mi << 1, qB = qA + 1;
                const float pA0 = (d0.x >= thr[qA]) ? a1c[qA]*d0.y : a2c[qA]*d0.z;
                const float pA1 = (d1.x >= thr[qA]) ? a1c[qA]*d1.y : a2c[qA]*d1.z;
                const float pB0 = (d0.x >= thr[qB]) ? a1c[qB]*d0.y : a2c[qB]*d0.z;
                const float pB1 = (d1.x >= thr[qB]) ? a1c[qB]*d1.y : a2c[qB]*d1.z;
                const float pA8 = (d8.x >= thr[qA]) ? a1c[qA]*d8.y : a2c[qA]*d8.z;
                const float pA9 = (d9.x >= thr[qA]) ? a1c[qA]*d9.y : a2c[qA]*d9.z;
                const float pB8 = (d8.x >= thr[qB]) ? a1c[qB]*d8.y : a2c[qB]*d8.z;
                const float pB9 = (d9.x >= thr[qB]) ? a1c[qB]*d9.y : a2c[qB]*d9.z;
                uint32_t af[4];
                af[0] = pack2h(pA0, pA1);
                af[1] = pack2h(pB0, pB1);
                af[2] = pack2h(pA8, pA9);
                af[3] = pack2h(pB8, pB9);
                #pragma unroll
                for (int ni = 0; ni < 4; ni++)
                    mma16(acc[mi][ni], af, bf[ni]);
            }
        }
    }

    #pragma unroll
    for (int mi = 0; mi < 2; mi++) {
        #pragma unroll
        for (int half = 0; half < 2; half++) {
            const int row = i0 + wm + (mi << 4) + g + (half << 3);
            float* op = g_att + ((size_t)bh * Ssz + row) * HDim;
            #pragma unroll
            for (int ni = 0; ni < 4; ni++) {
                const int col = wn + (ni << 3) + (t << 1);
                *(float2*)(op + col) =
                    make_float2(acc[mi][ni][half*2], acc[mi][ni][half*2+1]);
            }
        }
    }
}

// ---------------------------------------------------------------------------
// LayerNorms: one WARP per row of 512; 16 elems/thread; shfl-only reduction
// ---------------------------------------------------------------------------
__global__ __launch_bounds__(256) void ln1_kernel(
    const float* __restrict__ x,
    const float* __restrict__ gw, const float* __restrict__ bw)
{
    const int m    = (blockIdx.x << 3) + (threadIdx.x >> 5);
    const int lane = threadIdx.x & 31;
    const int bb = m >> 9, s = m & 511;

    float v[16];
    float s1 = 0.f, s2 = 0.f;
    #pragma unroll
    for (int u = 0; u < 4; u++) {
        const int d = (u << 7) + (lane << 2);
        const int hh = d >> 6, hd = d & 63;
        const float4 a  = *(const float4*)&g_att[((size_t)(((bb << 3) + hh) << 9) + s) * HDim + hd];
        const float4 xv = *(const float4*)&x[(size_t)m * Dsz + d];
        v[u*4+0] = a.x + xv.x; v[u*4+1] = a.y + xv.y;
        v[u*4+2] = a.z + xv.z; v[u*4+3] = a.w + xv.w;
        #pragma unroll
        for (int k = 0; k < 4; k++) { s1 += v[u*4+k]; s2 += v[u*4+k]*v[u*4+k]; }
    }
    #pragma unroll
    for (int off = 16; off; off >>= 1) {
        s1 += __shfl_xor_sync(0xffffffffu, s1, off);
        s2 += __shfl_xor_sync(0xffffffffu, s2, off);
    }
    const float mean = s1 * (1.0f / 512.0f);
    const float rstd = rsqrtf(s2 * (1.0f / 512.0f) - mean * mean + 1e-5f);

    #pragma unroll
    for (int u = 0; u < 4; u++) {
        const int d = (u << 7) + (lane << 2);
        const float4 gg = *(const float4*)&gw[d];
        const float4 bbv = *(const float4*)&bw[d];
        float4 o;
        o.x = (v[u*4+0] - mean) * rstd * gg.x + bbv.x;
        o.y = (v[u*4+1] - mean) * rstd * gg.y + bbv.y;
        o.z = (v[u*4+2] - mean) * rstd * gg.z + bbv.z;
        o.w = (v[u*4+3] - mean) * rstd * gg.w + bbv.w;
        *(float4*)&g_y[(size_t)m * Dsz + d] = o;
        *(uint2*)&g_y16[(size_t)m * Dsz + d] = make_uint2(pack2h(o.x, o.y), pack2h(o.z, o.w));
    }
}

__global__ __launch_bounds__(256) void ln2_kernel(
    const float* __restrict__ gw, const float* __restrict__ bw,
    float* __restrict__ out)
{
    const int m    = (blockIdx.x << 3) + (threadIdx.x >> 5);
    const int lane = threadIdx.x & 31;

    float v[16];
    float s1 = 0.f, s2 = 0.f;
    #pragma unroll
    for (int u = 0; u < 4; u++) {
        const int d = (u << 7) + (lane << 2);
        const float4 p = *(const float4*)&g_pre2[(size_t)m * Dsz + d];
        v[u*4+0] = p.x; v[u*4+1] = p.y; v[u*4+2] = p.z; v[u*4+3] = p.w;
        #pragma unroll
        for (int k = 0; k < 4; k++) { s1 += v[u*4+k]; s2 += v[u*4+k]*v[u*4+k]; }
    }
    #pragma unroll
    for (int off = 16; off; off >>= 1) {
        s1 += __shfl_xor_sync(0xffffffffu, s1, off);
        s2 += __shfl_xor_sync(0xffffffffu, s2, off);
    }
    const float mean = s1 * (1.0f / 512.0f);
    const float rstd = rsqrtf(s2 * (1.0f / 512.0f) - mean * mean + 1e-5f);

    #pragma unroll
    for (int u = 0; u < 4; u++) {
        const int d = (u << 7) + (lane << 2);
        const float4 gg = *(const float4*)&gw[d];
        const float4 bbv = *(const float4*)&bw[d];
        float4 o;
        o.x = (v[u*4+0] - mean) * rstd * gg.x + bbv.x;
        o.y = (v[u*4+1] - mean) * rstd * gg.y + bbv.y;
        o.z = (v[u*4+2] - mean) * rstd * gg.z + bbv.z;
        o.w = (v[u*4+3] - mean) * rstd * gg.w + bbv.w;
        *(float4*)&out[(size_t)m * Dsz + d] = o;
    }
}

// ---------------------------------------------------------------------------
// Launch. adj/sem_W/sem_b are provably dead (softmax output can never be
// exactly 0, so the mask is the identity) and are not read.
// ---------------------------------------------------------------------------
extern "C" void kernel_launch(void* const* d_in, const int* in_sizes, int n_in,
                              void* d_out, int out_size)
{
    const float* x     = (const float*)d_in[0];
    const float* w_W   = (const float*)d_in[2];
    const float* w_b   = (const float*)d_in[3];
    const float* a_w   = (const float*)d_in[4];
    const float* ff1_W = (const float*)d_in[7];
    const float* ff1_b = (const float*)d_in[8];
    const float* ff2_W = (const float*)d_in[9];
    const float* ff2_b = (const float*)d_in[10];
    const float* ln1_g = (const float*)d_in[11];
    const float* ln1_b = (const float*)d_in[12];
    const float* ln2_g = (const float*)d_in[13];
    const float* ln2_b = (const float*)d_in[14];
    float* out = (float*)d_out;

    __half* dx16;  cudaGetSymbolAddress((void**)&dx16,  g_x16);
    __half* dw16;  cudaGetSymbolAddress((void**)&dw16,  g_w16);
    __half* d1w16; cudaGetSymbolAddress((void**)&d1w16, g_f1w16);
    __half* d2w16; cudaGetSymbolAddress((void**)&d2w16, g_f2w16);
    __half* dy16;  cudaGetSymbolAddress((void**)&dy16,  g_y16);
    __half* dff16; cudaGetSymbolAddress((void**)&dff16, g_ff16);

    cudaFuncSetAttribute(mm_mma<1>, cudaFuncAttributeMaxDynamicSharedMemorySize, MM_SMEM);
    cudaFuncSetAttribute(mm_mma<2>, cudaFuncAttributeMaxDynamicSharedMemorySize, MM_SMEM);
    cudaFuncSetAttribute(mm_mma<3>, cudaFuncAttributeMaxDynamicSharedMemorySize, MM_SMEM);

    // 0) fp32 -> fp16 conversions (single fused launch)
    const int n0 = Mrows*Dsz, n1 = Dsz*Dsz, n2 = 2*Dsz*Dsz, n3 = 2*Dsz*Dsz;
    f2h4_kernel<<<(n0+n1+n2+n3)/1024, 256>>>(x, dx16, n0, w_W, dw16, n1,
                                             ff1_W, d1w16, n2, ff2_W, d2w16, n3);

    // 1) h = x @ w_W^T + w_b -> fused transpose -> g_hT (bh,d,s)
    mm_mma<1><<<dim3(Dsz/128, Mrows/128), 256, MM_SMEM>>>(dx16, dw16, w_b, Dsz, Dsz);
    // 2) src/dst projections (from g_hT)
    src_dst_kernel<<<Bsz*Hh, 256>>>(a_w);
    // 3) fused GAT attention -> g_att
    attn_mma_kernel<<<dim3(Ssz/128, Bsz*Hh), 256>>>();
    // 4) LN1(att + x) -> g_y (fp32) + g_y16
    ln1_kernel<<<Mrows/8, 256>>>(x, ln1_g, ln1_b);
    // 5) g_ff16 = GeLU(y @ ff1_W^T + ff1_b)
    mm_mma<2><<<dim3(2*Dsz/128, Mrows/128), 256, MM_SMEM>>>(dy16, d1w16, ff1_b, 2*Dsz, Dsz);
    // 6) g_pre2 = ff @ ff2_W^T + ff2_b + y
    mm_mma<3><<<dim3(Dsz/128, Mrows/128), 256, MM_SMEM>>>(dff16, d2w16, ff2_b, Dsz, 2*Dsz);
    // 7) LN2 -> out
    ln2_kernel<<<Mrows/8, 256>>>(ln2_g, ln2_b, out);
}